// round 1
// baseline (speedup 1.0000x reference)
#include <cuda_runtime.h>

#define Bn 256
#define Tn 256
#define Cn 256
#define Hn 64

// Scratch (device globals: no allocation in kernel_launch allowed)
__device__ float g_q[Bn*Tn*Hn];   // 16 MB
__device__ float g_k[Bn*Tn*Hn];   // 16 MB (pre-scaled by 1/8)
__device__ float g_v[Bn*Tn*Hn];   // 16 MB
__device__ float g_p[Bn*Tn*Tn];   // 64 MB: P[b,t,d] = q[b,t] . E[d], d in [0,256)

// ---------------------------------------------------------------------------
// Kernel 1: q/k/v projections. grid = (65536/128, 3), block = 256.
// M-tile 128, N = 64 (full H), K-tile 32. Thread tile 8x4.
// ---------------------------------------------------------------------------
__global__ __launch_bounds__(256) void qkv_kernel(
    const float* __restrict__ x, const float* __restrict__ Wq,
    const float* __restrict__ Wk, const float* __restrict__ Wv)
{
    __shared__ float xs[128][33];
    __shared__ float ws[32][65];
    const int which = blockIdx.y;
    const float* W = (which == 0) ? Wq : (which == 1) ? Wk : Wv;
    float* outp    = (which == 0) ? g_q : (which == 1) ? g_k : g_v;
    const float scl = (which == 1) ? 0.125f : 1.0f;  // scale folded into k
    const int row0 = blockIdx.x * 128;
    const int tid = threadIdx.x;
    const int ty = tid >> 4, tx = tid & 15;

    float acc[8][4] = {};
    for (int ct = 0; ct < Cn; ct += 32) {
        #pragma unroll
        for (int i = 0; i < 16; i++) {
            int idx = tid + i * 256;
            int r = idx >> 5, cc = idx & 31;
            xs[r][cc] = x[(row0 + r) * Cn + ct + cc];
        }
        #pragma unroll
        for (int i = 0; i < 8; i++) {
            int idx = tid + i * 256;
            int r = idx >> 6, h = idx & 63;
            ws[r][h] = W[(ct + r) * Hn + h];
        }
        __syncthreads();
        #pragma unroll
        for (int kk = 0; kk < 32; kk++) {
            float a[8], bb[4];
            #pragma unroll
            for (int i = 0; i < 8; i++) a[i] = xs[ty * 8 + i][kk];
            #pragma unroll
            for (int j = 0; j < 4; j++) bb[j] = ws[kk][tx * 4 + j];
            #pragma unroll
            for (int i = 0; i < 8; i++)
                #pragma unroll
                for (int j = 0; j < 4; j++)
                    acc[i][j] += a[i] * bb[j];
        }
        __syncthreads();
    }
    #pragma unroll
    for (int i = 0; i < 8; i++)
        #pragma unroll
        for (int j = 0; j < 4; j++)
            outp[(row0 + ty * 8 + i) * Hn + tx * 4 + j] = acc[i][j] * scl;
}

// ---------------------------------------------------------------------------
// Kernel 2: P[row, d] = q[row] . E[d]  for d in [0,256).
// grid = 65536/64, block = 256. Whole E (256x64) in smem. Thread tile 4x16
// with d strided by 16 (conflict-free Es reads).
// ---------------------------------------------------------------------------
__global__ __launch_bounds__(256) void pos_kernel(const float* __restrict__ E)
{
    extern __shared__ float sm[];
    float (*qs)[65] = (float(*)[65])sm;              // 64 x 65
    float (*Es)[65] = (float(*)[65])(sm + 64 * 65);  // 256 x 65
    const int row0 = blockIdx.x * 64;
    const int tid = threadIdx.x;

    #pragma unroll
    for (int i = 0; i < 16; i++) {
        int idx = tid + i * 256;
        int r = idx >> 6, h = idx & 63;
        qs[r][h] = g_q[(row0 + r) * Hn + h];
    }
    #pragma unroll
    for (int i = 0; i < 64; i++) {
        int idx = tid + i * 256;
        int d = idx >> 6, h = idx & 63;
        Es[d][h] = E[d * Hn + h];
    }
    __syncthreads();

    const int ty = tid >> 4, tx = tid & 15;
    float acc[4][16] = {};
    #pragma unroll 4
    for (int h = 0; h < Hn; h++) {
        float a[4];
        #pragma unroll
        for (int i = 0; i < 4; i++) a[i] = qs[ty * 4 + i][h];
        #pragma unroll
        for (int j = 0; j < 16; j++) {
            float e = Es[tx + 16 * j][h];
            #pragma unroll
            for (int i = 0; i < 4; i++) acc[i][j] += a[i] * e;
        }
    }
    #pragma unroll
    for (int i = 0; i < 4; i++)
        #pragma unroll
        for (int j = 0; j < 16; j++)
            g_p[(long)(row0 + ty * 4 + i) * 256 + tx + 16 * j] = acc[i][j];
}

// ---------------------------------------------------------------------------
// Kernel 3: attention. grid = (B, T/64), block = 256.
// Full score row (64 queries x 256 keys) lives in smem -> exact softmax,
// no online rescaling. Causal tiles skipped for both QK^T and PV.
// ---------------------------------------------------------------------------
__global__ __launch_bounds__(256) void attn_kernel(float* __restrict__ out)
{
    extern __shared__ float sm[];
    float (*sc)[257] = (float(*)[257])sm;                      // 64 x 257
    float (*qs)[65]  = (float(*)[65])(sm + 64 * 257);          // 64 x 65
    float (*kv)[65]  = (float(*)[65])(sm + 64 * 257 + 64 * 65);// 64 x 65

    const int b  = blockIdx.x;
    const int tt = blockIdx.y;
    const int t0 = tt * 64;
    const int tid = threadIdx.x;
    const int ty = tid >> 4, tx = tid & 15;

    // init scores to very negative (covers tiles st > tt)
    for (int i = tid; i < 64 * 257; i += 256) sm[i] = -1e30f;

    // load q tile
    #pragma unroll
    for (int i = 0; i < 16; i++) {
        int idx = tid + i * 256;
        int r = idx >> 6, h = idx & 63;
        qs[r][h] = g_q[((long)(b * Tn + t0 + r)) * Hn + h];
    }
    __syncthreads();

    // ---- score phase: content (q.k') + position gather (P) ----
    for (int st = 0; st <= tt; st++) {
        #pragma unroll
        for (int i = 0; i < 16; i++) {
            int idx = tid + i * 256;
            int r = idx >> 6, h = idx & 63;
            kv[r][h] = g_k[((long)(b * Tn + st * 64 + r)) * Hn + h];
        }
        __syncthreads();

        float acc[4][4] = {};
        #pragma unroll 8
        for (int h = 0; h < Hn; h++) {
            float a[4], bb[4];
            #pragma unroll
            for (int i = 0; i < 4; i++) a[i] = qs[ty * 4 + i][h];
            #pragma unroll
            for (int j = 0; j < 4; j++) bb[j] = kv[tx * 4 + j][h];
            #pragma unroll
            for (int i = 0; i < 4; i++)
                #pragma unroll
                for (int j = 0; j < 4; j++)
                    acc[i][j] += a[i] * bb[j];
        }
        #pragma unroll
        for (int i = 0; i < 4; i++) {
            int t = t0 + ty * 4 + i;            // global query index
            #pragma unroll
            for (int j = 0; j < 4; j++) {
                int s = st * 64 + tx * 4 + j;   // global key index
                float val = -1e30f;
                if (s <= t) {
                    float p = g_p[((long)(b * Tn + t)) * 256 + (s - t + 255)];
                    val = acc[i][j] + p;
                }
                sc[ty * 4 + i][s] = val;
            }
        }
        __syncthreads();
    }

    // ---- softmax: 8 warps x 8 rows ----
    {
        const int warp = tid >> 5, lane = tid & 31;
        for (int r = warp * 8; r < warp * 8 + 8; r++) {
            float m = -1e30f;
            #pragma unroll
            for (int s = lane; s < 256; s += 32) m = fmaxf(m, sc[r][s]);
            #pragma unroll
            for (int o = 16; o; o >>= 1) m = fmaxf(m, __shfl_xor_sync(0xffffffffu, m, o));
            float sum = 0.f;
            #pragma unroll
            for (int s = lane; s < 256; s += 32) {
                float e = __expf(sc[r][s] - m);
                sc[r][s] = e;
                sum += e;
            }
            #pragma unroll
            for (int o = 16; o; o >>= 1) sum += __shfl_xor_sync(0xffffffffu, sum, o);
            float inv = 1.0f / sum;
            #pragma unroll
            for (int s = lane; s < 256; s += 32) sc[r][s] *= inv;
        }
    }
    __syncthreads();

    // ---- out = wei @ v ----
    float oacc[4][4] = {};
    for (int st = 0; st <= tt; st++) {
        #pragma unroll
        for (int i = 0; i < 16; i++) {
            int idx = tid + i * 256;
            int r = idx >> 6, h = idx & 63;
            kv[r][h] = g_v[((long)(b * Tn + st * 64 + r)) * Hn + h];
        }
        __syncthreads();
        #pragma unroll 8
        for (int s = 0; s < 64; s++) {
            float w[4], vv[4];
            #pragma unroll
            for (int i = 0; i < 4; i++) w[i] = sc[ty * 4 + i][st * 64 + s];
            #pragma unroll
            for (int j = 0; j < 4; j++) vv[j] = kv[s][tx * 4 + j];
            #pragma unroll
            for (int i = 0; i < 4; i++)
                #pragma unroll
                for (int j = 0; j < 4; j++)
                    oacc[i][j] += w[i] * vv[j];
        }
        __syncthreads();
    }

    #pragma unroll
    for (int i = 0; i < 4; i++)
        #pragma unroll
        for (int j = 0; j < 4; j++)
            out[((long)(b * Tn + t0 + ty * 4 + i)) * Hn + tx * 4 + j] = oacc[i][j];
}

// ---------------------------------------------------------------------------
extern "C" void kernel_launch(void* const* d_in, const int* in_sizes, int n_in,
                              void* d_out, int out_size)
{
    const float* x  = (const float*)d_in[0];
    const float* Wk = (const float*)d_in[1];
    const float* Wq = (const float*)d_in[2];
    const float* Wv = (const float*)d_in[3];
    const float* E  = (const float*)d_in[4];
    float* out = (float*)d_out;

    // Kernel 1: projections (q, k*1/8, v)
    qkv_kernel<<<dim3(Bn * Tn / 128, 3), 256>>>(x, Wq, Wk, Wv);

    // Kernel 2: P = q @ E[0:256]^T
    const int psm = (64 * 65 + 256 * 65) * (int)sizeof(float);   // 83200 B
    cudaFuncSetAttribute(pos_kernel, cudaFuncAttributeMaxDynamicSharedMemorySize, psm);
    pos_kernel<<<Bn * Tn / 64, 256, psm>>>(E);

    // Kernel 3: attention
    const int asmem = (64 * 257 + 2 * 64 * 65) * (int)sizeof(float); // 99072 B
    cudaFuncSetAttribute(attn_kernel, cudaFuncAttributeMaxDynamicSharedMemorySize, asmem);
    attn_kernel<<<dim3(Bn, Tn / 64), 256, asmem>>>(out);
}

// round 2
// speedup vs baseline: 1.0569x; 1.0569x over previous
#include <cuda_runtime.h>

#define Bn 256
#define Tn 256
#define Cn 256
#define Hn 64

// Scratch (device globals: no allocation allowed)
__device__ float g_q[Bn*Tn*Hn];    // 16 MB, unscaled q
__device__ float g_k[Bn*Tn*Hn];    // 16 MB, k * (1/8)
__device__ float g_v[Bn*Tn*Hn];    // 16 MB
__device__ float g_p[Bn*Tn*256];   // 64 MB, P[b,t,d] = q[b,t].E[d]

// Swizzled [K][M] layouts (M = row length, power of two). XOR lives in bank
// bits 2..4 so transposed scalar stores are <=2-way and float4 reads clean.
__device__ __forceinline__ int swz128(int k, int m) {
    return k * 128 + (m ^ (((k >> 2) & 7) << 2));
}
__device__ __forceinline__ int swz64(int k, int m) {
    return k * 64 + (m ^ (((k >> 2) & 7) << 2));
}

// ---------------------------------------------------------------------------
// Kernel 1: q/k/v projections. grid=(512,3), block=256.
// Block tile M=128, N=64, K-tile=64. Warps 4(m)x2(n) -> 32x32 squares.
// Thread tile 4x8.
// ---------------------------------------------------------------------------
__global__ __launch_bounds__(256) void qkv_kernel(
    const float* __restrict__ x, const float* __restrict__ Wq,
    const float* __restrict__ Wk, const float* __restrict__ Wv)
{
    extern __shared__ float smf[];
    float* xs = smf;                                   // swz128: [64 k][128 m]
    float (*ws)[68] = (float(*)[68])(smf + 64 * 128);  // [64 k][64 n] natural

    const int which = blockIdx.y;
    const float* W = (which == 0) ? Wq : (which == 1) ? Wk : Wv;
    float* outp    = (which == 0) ? g_q : (which == 1) ? g_k : g_v;
    const float scl = (which == 1) ? 0.125f : 1.0f;
    const int row0 = blockIdx.x * 128;
    const int tid = threadIdx.x;
    const int w = tid >> 5, l = tid & 31;
    const int wm = w >> 1, wn = w & 1;
    const int lm = l >> 2, ln = l & 3;
    const int m0 = wm * 32 + lm * 4;
    const int n0 = wn * 32 + ln * 8;

    float acc[4][8] = {};
    for (int ct = 0; ct < Cn; ct += 64) {
        #pragma unroll
        for (int i = 0; i < 8; i++) {
            int f = tid + i * 256;
            int r = f >> 4, c4 = (f & 15) << 2;
            float4 vx = *(const float4*)(x + (row0 + r) * Cn + ct + c4);
            xs[swz128(c4 + 0, r)] = vx.x;
            xs[swz128(c4 + 1, r)] = vx.y;
            xs[swz128(c4 + 2, r)] = vx.z;
            xs[swz128(c4 + 3, r)] = vx.w;
        }
        #pragma unroll
        for (int i = 0; i < 4; i++) {
            int f = tid + i * 256;
            int r = f >> 4, c4 = (f & 15) << 2;
            *(float4*)&ws[r][c4] = *(const float4*)(W + (ct + r) * Hn + c4);
        }
        __syncthreads();

        #pragma unroll 8
        for (int kk = 0; kk < 64; kk++) {
            float4 a  = *(const float4*)(xs + swz128(kk, m0));
            float4 b0 = *(const float4*)&ws[kk][n0];
            float4 b1 = *(const float4*)&ws[kk][n0 + 4];
            float av[4] = {a.x, a.y, a.z, a.w};
            float bv[8] = {b0.x, b0.y, b0.z, b0.w, b1.x, b1.y, b1.z, b1.w};
            #pragma unroll
            for (int i = 0; i < 4; i++)
                #pragma unroll
                for (int j = 0; j < 8; j++)
                    acc[i][j] += av[i] * bv[j];
        }
        __syncthreads();
    }

    #pragma unroll
    for (int i = 0; i < 4; i++) {
        float4 o0, o1;
        o0.x = acc[i][0] * scl; o0.y = acc[i][1] * scl;
        o0.z = acc[i][2] * scl; o0.w = acc[i][3] * scl;
        o1.x = acc[i][4] * scl; o1.y = acc[i][5] * scl;
        o1.z = acc[i][6] * scl; o1.w = acc[i][7] * scl;
        float* po = outp + (row0 + m0 + i) * Hn + n0;
        *(float4*)po = o0;
        *(float4*)(po + 4) = o1;
    }
}

// ---------------------------------------------------------------------------
// Kernel 2: P[row, d] = q[row] . E[d]. grid=(1024, 2), block=256.
// Block tile M=64 rows, N=128 d-cols (half of 256). K=64 single tile.
// Causal skip: block & warp level (only d >= 192 - t0 is ever read).
// ---------------------------------------------------------------------------
__global__ __launch_bounds__(256) void pos_kernel(const float* __restrict__ E)
{
    const int row0  = blockIdx.x * 64;
    const int t0    = (blockIdx.x & 3) * 64;
    const int nbase = blockIdx.y * 128;
    const int dmin  = 192 - t0;
    if (nbase + 127 < dmin) return;   // uniform: whole block masked

    extern __shared__ float smf[];
    float* qs = smf;              // swz64:  [64 k(h)][64 m(row)]
    float* Es = smf + 64 * 64;    // swz128: [64 k(h)][128 m(d-local)]
    const int tid = threadIdx.x;

    #pragma unroll
    for (int i = 0; i < 4; i++) {
        int f = tid + i * 256;
        int r = f >> 4, h4 = (f & 15) << 2;
        float4 vq = *(const float4*)(g_q + (row0 + r) * Hn + h4);
        qs[swz64(h4 + 0, r)] = vq.x;
        qs[swz64(h4 + 1, r)] = vq.y;
        qs[swz64(h4 + 2, r)] = vq.z;
        qs[swz64(h4 + 3, r)] = vq.w;
    }
    #pragma unroll
    for (int i = 0; i < 8; i++) {
        int f = tid + i * 256;
        int d = f >> 4, h4 = (f & 15) << 2;
        float4 ve = *(const float4*)(E + (nbase + d) * Hn + h4);
        Es[swz128(h4 + 0, d)] = ve.x;
        Es[swz128(h4 + 1, d)] = ve.y;
        Es[swz128(h4 + 2, d)] = ve.z;
        Es[swz128(h4 + 3, d)] = ve.w;
    }
    __syncthreads();

    const int w = tid >> 5, l = tid & 31;
    const int wm = w >> 2, wn = w & 3;      // 2(m) x 4(n) warps, 32x32 each
    const int lm = l >> 2, ln = l & 3;
    const int m0 = wm * 32 + lm * 4;
    const int n0 = wn * 32 + ln * 8;        // local d

    if (nbase + (wn * 32 + 31) < dmin) return;  // warp-uniform skip

    float acc[4][8] = {};
    #pragma unroll 8
    for (int kk = 0; kk < 64; kk++) {
        float4 a  = *(const float4*)(qs + swz64(kk, m0));
        float4 b0 = *(const float4*)(Es + swz128(kk, n0));
        float4 b1 = *(const float4*)(Es + swz128(kk, n0 + 4));
        float av[4] = {a.x, a.y, a.z, a.w};
        float bv[8] = {b0.x, b0.y, b0.z, b0.w, b1.x, b1.y, b1.z, b1.w};
        #pragma unroll
        for (int i = 0; i < 4; i++)
            #pragma unroll
            for (int j = 0; j < 8; j++)
                acc[i][j] += av[i] * bv[j];
    }

    #pragma unroll
    for (int i = 0; i < 4; i++) {
        float* pp = g_p + (long)(row0 + m0 + i) * 256 + nbase + n0;
        float4 o0 = {acc[i][0], acc[i][1], acc[i][2], acc[i][3]};
        float4 o1 = {acc[i][4], acc[i][5], acc[i][6], acc[i][7]};
        *(float4*)pp = o0;
        *(float4*)(pp + 4) = o1;
    }
}

// ---------------------------------------------------------------------------
// Kernel 3: attention. grid=(256, 4), block=256.
// 64 query rows per block; full 256-key score row in smem; causal tile skip.
// Warps 2(m) x 4(n); thread tile 4x4.
// ---------------------------------------------------------------------------
__global__ __launch_bounds__(256) void attn_kernel(float* __restrict__ out)
{
    extern __shared__ float smf[];
    float (*sc)[257] = (float(*)[257])smf;         // 64 x 257
    float* qs = smf + 64 * 257;                    // swz64 [64 h][64 m]
    float* kv = qs + 64 * 64;                      // k: swz64 [64][64]; v: [64][68]
    float (*vs)[68] = (float(*)[68])kv;

    const int b  = blockIdx.x;
    const int tt = blockIdx.y;
    const int t0 = tt * 64;
    const int tid = threadIdx.x;
    const int w = tid >> 5, l = tid & 31;
    const int wm = w >> 2, wn = w & 3;
    const int lm = l >> 2, ln = l & 3;
    const int m0 = wm * 32 + lm * 4;
    const int n0 = wn * 16 + ln * 4;

    for (int i = tid; i < 64 * 257; i += 256) smf[i] = -1e30f;

    #pragma unroll
    for (int i = 0; i < 4; i++) {
        int f = tid + i * 256;
        int r = f >> 4, h4 = (f & 15) << 2;
        float4 vq = *(const float4*)(g_q + ((long)(b * Tn + t0 + r)) * Hn + h4);
        qs[swz64(h4 + 0, r)] = vq.x;
        qs[swz64(h4 + 1, r)] = vq.y;
        qs[swz64(h4 + 2, r)] = vq.z;
        qs[swz64(h4 + 3, r)] = vq.w;
    }
    __syncthreads();

    // ---- score phase ----
    for (int st = 0; st <= tt; st++) {
        #pragma unroll
        for (int i = 0; i < 4; i++) {
            int f = tid + i * 256;
            int r = f >> 4, h4 = (f & 15) << 2;
            float4 vk = *(const float4*)(g_k + ((long)(b * Tn + st * 64 + r)) * Hn + h4);
            kv[swz64(h4 + 0, r)] = vk.x;
            kv[swz64(h4 + 1, r)] = vk.y;
            kv[swz64(h4 + 2, r)] = vk.z;
            kv[swz64(h4 + 3, r)] = vk.w;
        }
        __syncthreads();

        float acc[4][4] = {};
        #pragma unroll 8
        for (int kk = 0; kk < 64; kk++) {
            float4 a = *(const float4*)(qs + swz64(kk, m0));
            float4 bq = *(const float4*)(kv + swz64(kk, n0));
            float av[4] = {a.x, a.y, a.z, a.w};
            float bv[4] = {bq.x, bq.y, bq.z, bq.w};
            #pragma unroll
            for (int i = 0; i < 4; i++)
                #pragma unroll
                for (int j = 0; j < 4; j++)
                    acc[i][j] += av[i] * bv[j];
        }

        #pragma unroll
        for (int i = 0; i < 4; i++) {
            int t = t0 + m0 + i;
            const float* prow = g_p + ((long)(b * Tn + t)) * 256;
            #pragma unroll
            for (int j = 0; j < 4; j++) {
                int s = st * 64 + n0 + j;
                float val = -1e30f;
                if (s <= t) val = acc[i][j] + prow[s - t + 255];
                sc[m0 + i][s] = val;
            }
        }
        __syncthreads();
    }

    // ---- softmax: 8 warps x 8 rows ----
    {
        const int warp = tid >> 5, lane = tid & 31;
        for (int r = warp * 8; r < warp * 8 + 8; r++) {
            float m = -1e30f;
            #pragma unroll
            for (int s = lane; s < 256; s += 32) m = fmaxf(m, sc[r][s]);
            #pragma unroll
            for (int o = 16; o; o >>= 1) m = fmaxf(m, __shfl_xor_sync(0xffffffffu, m, o));
            float sum = 0.f;
            #pragma unroll
            for (int s = lane; s < 256; s += 32) {
                float e = __expf(sc[r][s] - m);
                sc[r][s] = e;
                sum += e;
            }
            #pragma unroll
            for (int o = 16; o; o >>= 1) sum += __shfl_xor_sync(0xffffffffu, sum, o);
            float inv = 1.0f / sum;
            #pragma unroll
            for (int s = lane; s < 256; s += 32) sc[r][s] *= inv;
        }
    }
    __syncthreads();

    // ---- out = wei @ v ----
    float oacc[4][4] = {};
    for (int st = 0; st <= tt; st++) {
        #pragma unroll
        for (int i = 0; i < 4; i++) {
            int f = tid + i * 256;
            int r = f >> 4, h4 = (f & 15) << 2;
            *(float4*)&vs[r][h4] =
                *(const float4*)(g_v + ((long)(b * Tn + st * 64 + r)) * Hn + h4);
        }
        __syncthreads();

        #pragma unroll 8
        for (int s = 0; s < 64; s++) {
            float4 vv = *(const float4*)&vs[s][n0];
            float bv[4] = {vv.x, vv.y, vv.z, vv.w};
            #pragma unroll
            for (int i = 0; i < 4; i++) {
                float wgt = sc[m0 + i][st * 64 + s];
                #pragma unroll
                for (int j = 0; j < 4; j++)
                    oacc[i][j] += wgt * bv[j];
            }
        }
        __syncthreads();
    }

    #pragma unroll
    for (int i = 0; i < 4; i++) {
        float4 o = {oacc[i][0], oacc[i][1], oacc[i][2], oacc[i][3]};
        *(float4*)(out + ((long)(b * Tn + t0 + m0 + i)) * Hn + n0) = o;
    }
}

// ---------------------------------------------------------------------------
extern "C" void kernel_launch(void* const* d_in, const int* in_sizes, int n_in,
                              void* d_out, int out_size)
{
    const float* x  = (const float*)d_in[0];
    const float* Wk = (const float*)d_in[1];
    const float* Wq = (const float*)d_in[2];
    const float* Wv = (const float*)d_in[3];
    const float* E  = (const float*)d_in[4];
    float* out = (float*)d_out;

    const int qkv_sm = (64 * 128 + 64 * 68) * (int)sizeof(float);      // 50176
    cudaFuncSetAttribute(qkv_kernel, cudaFuncAttributeMaxDynamicSharedMemorySize, qkv_sm);
    qkv_kernel<<<dim3(Bn * Tn / 128, 3), 256, qkv_sm>>>(x, Wq, Wk, Wv);

    const int pos_sm = (64 * 64 + 64 * 128) * (int)sizeof(float);      // 49152
    cudaFuncSetAttribute(pos_kernel, cudaFuncAttributeMaxDynamicSharedMemorySize, pos_sm);
    pos_kernel<<<dim3(Bn * Tn / 64, 2), 256, pos_sm>>>(E);

    const int attn_sm = (64 * 257 + 64 * 64 + 64 * 68) * (int)sizeof(float); // 99584
    cudaFuncSetAttribute(attn_kernel, cudaFuncAttributeMaxDynamicSharedMemorySize, attn_sm);
    attn_kernel<<<dim3(Bn, Tn / 64), 256, attn_sm>>>(out);
}

// round 4
// speedup vs baseline: 1.3035x; 1.2333x over previous
#include <cuda_runtime.h>
#include <cuda_bf16.h>
#include <cstdint>

#define Bn 256
#define Tn 256
#define Cn 256
#define Hn 64

// ---------------- scratch ----------------
__device__ float g_q[Bn*Tn*Hn];
__device__ float g_k[Bn*Tn*Hn];    // k * (1/8), scale folded into W
__device__ float g_v[Bn*Tn*Hn];
__device__ float g_p[Bn*Tn*256];   // P[b,t,d] = q[b,t].E[d]

// ---------------- helpers ----------------
__device__ __forceinline__ void mma_bf16(float* c, const uint32_t* a, const uint32_t* b) {
    asm volatile(
        "mma.sync.aligned.m16n8k16.row.col.f32.bf16.bf16.f32 "
        "{%0,%1,%2,%3}, {%4,%5,%6,%7}, {%8,%9}, {%0,%1,%2,%3};"
        : "+f"(c[0]), "+f"(c[1]), "+f"(c[2]), "+f"(c[3])
        : "r"(a[0]), "r"(a[1]), "r"(a[2]), "r"(a[3]), "r"(b[0]), "r"(b[1]));
}
__device__ __forceinline__ void split_bf(float v, __nv_bfloat16& h, __nv_bfloat16& l) {
    h = __float2bfloat16(v);
    l = __float2bfloat16(v - __bfloat162float(h));
}

// ---------------------------------------------------------------------------
// Kernel 1: qkv projections via bf16x3 mma. grid=(512,3), block=256.
// Block tile 128(m) x 64(n), K chunks of 32. Warps 4m x 2n, warp tile 32x32.
// smem: hi/lo A [128][40], hi/lo B(transposed W) [64][40], pad-40 rows.
// ---------------------------------------------------------------------------
__global__ __launch_bounds__(256) void qkv_kernel(
    const float* __restrict__ x, const float* __restrict__ Wq,
    const float* __restrict__ Wk, const float* __restrict__ Wv)
{
    __shared__ __nv_bfloat16 Ah[128*40], Al[128*40], Bh[64*40], Bl[64*40];

    const int which = blockIdx.y;
    const float* W = (which == 0) ? Wq : (which == 1) ? Wk : Wv;
    float* outp    = (which == 0) ? g_q : (which == 1) ? g_k : g_v;
    const float scl = (which == 1) ? 0.125f : 1.0f;
    const int row0 = blockIdx.x * 128;
    const int tid = threadIdx.x, w = tid >> 5, lane = tid & 31;
    const int wm = w >> 1, wn = w & 1;
    const int g = lane >> 2, l2 = lane & 3;

    float acc[2][4][4] = {};

    for (int ct = 0; ct < Cn; ct += 32) {
        // prefetch to regs
        float4 xv[4];
        #pragma unroll
        for (int i = 0; i < 4; i++) {
            int f = tid + i * 256;
            int r = f >> 3, c4 = (f & 7) << 2;
            xv[i] = *(const float4*)(x + (row0 + r) * Cn + ct + c4);
        }
        float4 wv[2];
        #pragma unroll
        for (int i = 0; i < 2; i++) {
            int f = tid + i * 256;
            int kr = f >> 4, n4 = (f & 15) << 2;
            wv[i] = *(const float4*)(W + (ct + kr) * Hn + n4);
        }
        __syncthreads();   // prior chunk's compute done

        #pragma unroll
        for (int i = 0; i < 4; i++) {
            int f = tid + i * 256;
            int r = f >> 3, c4 = (f & 7) << 2;
            float vv[4] = {xv[i].x, xv[i].y, xv[i].z, xv[i].w};
            #pragma unroll
            for (int j = 0; j < 4; j++) {
                __nv_bfloat16 h, l;
                split_bf(vv[j], h, l);
                Ah[r * 40 + c4 + j] = h;
                Al[r * 40 + c4 + j] = l;
            }
        }
        #pragma unroll
        for (int i = 0; i < 2; i++) {
            int f = tid + i * 256;
            int kr = f >> 4, n4 = (f & 15) << 2;
            float vv[4] = {wv[i].x * scl, wv[i].y * scl, wv[i].z * scl, wv[i].w * scl};
            #pragma unroll
            for (int j = 0; j < 4; j++) {
                __nv_bfloat16 h, l;
                split_bf(vv[j], h, l);
                Bh[(n4 + j) * 40 + kr] = h;   // transposed [n][k]
                Bl[(n4 + j) * 40 + kr] = l;
            }
        }
        __syncthreads();

        #pragma unroll
        for (int ks = 0; ks < 32; ks += 16) {
            uint32_t ah[2][4], al[2][4], bh[4][2], bl[4][2];
            #pragma unroll
            for (int mi = 0; mi < 2; mi++) {
                int r = wm * 32 + mi * 16 + g;
                int b0 = r * 40 + ks + l2 * 2;
                ah[mi][0] = *(const uint32_t*)&Ah[b0];
                ah[mi][1] = *(const uint32_t*)&Ah[b0 + 8 * 40];
                ah[mi][2] = *(const uint32_t*)&Ah[b0 + 8];
                ah[mi][3] = *(const uint32_t*)&Ah[b0 + 8 * 40 + 8];
                al[mi][0] = *(const uint32_t*)&Al[b0];
                al[mi][1] = *(const uint32_t*)&Al[b0 + 8 * 40];
                al[mi][2] = *(const uint32_t*)&Al[b0 + 8];
                al[mi][3] = *(const uint32_t*)&Al[b0 + 8 * 40 + 8];
            }
            #pragma unroll
            for (int ni = 0; ni < 4; ni++) {
                int n = wn * 32 + ni * 8 + g;
                int b0 = n * 40 + ks + l2 * 2;
                bh[ni][0] = *(const uint32_t*)&Bh[b0];
                bh[ni][1] = *(const uint32_t*)&Bh[b0 + 8];
                bl[ni][0] = *(const uint32_t*)&Bl[b0];
                bl[ni][1] = *(const uint32_t*)&Bl[b0 + 8];
            }
            #pragma unroll
            for (int mi = 0; mi < 2; mi++)
                #pragma unroll
                for (int ni = 0; ni < 4; ni++) {
                    mma_bf16(acc[mi][ni], ah[mi], bh[ni]);
                    mma_bf16(acc[mi][ni], ah[mi], bl[ni]);
                    mma_bf16(acc[mi][ni], al[mi], bh[ni]);
                }
        }
    }

    #pragma unroll
    for (int mi = 0; mi < 2; mi++) {
        int r = row0 + wm * 32 + mi * 16 + g;
        #pragma unroll
        for (int ni = 0; ni < 4; ni++) {
            int c = wn * 32 + ni * 8 + l2 * 2;
            float2 o0 = {acc[mi][ni][0], acc[mi][ni][1]};
            float2 o1 = {acc[mi][ni][2], acc[mi][ni][3]};
            *(float2*)(outp + r * Hn + c) = o0;
            *(float2*)(outp + (r + 8) * Hn + c) = o1;
        }
    }
}

// ---------------------------------------------------------------------------
// Kernel 2: P = q @ E^T via bf16x3 mma. grid=(1024,2), block=256.
// Block tile 64(m rows) x 128(n = d), K=64 single pass. Warps 2m x 4n,
// warp tile 32x32. Causal skip at block/warp/store level.
// smem: Ah/Al [64][72], Eh/El [128][72].
// ---------------------------------------------------------------------------
__global__ __launch_bounds__(256) void pos_kernel(const float* __restrict__ E)
{
    const int row0  = blockIdx.x * 64;
    const int t0    = row0 & 255;
    const int nbase = blockIdx.y * 128;
    const int dmin  = 192 - t0;
    if (nbase + 127 < dmin) return;

    extern __shared__ __nv_bfloat16 smb[];
    __nv_bfloat16* Ah = smb;                  // 64*72
    __nv_bfloat16* Al = Ah + 64 * 72;
    __nv_bfloat16* Eh = Al + 64 * 72;         // 128*72
    __nv_bfloat16* El = Eh + 128 * 72;

    const int tid = threadIdx.x, w = tid >> 5, lane = tid & 31;
    const int wm = w >> 2, wn = w & 3;
    const int g = lane >> 2, l2 = lane & 3;

    #pragma unroll
    for (int i = 0; i < 4; i++) {
        int f = tid + i * 256;
        int r = f >> 4, c4 = (f & 15) << 2;
        float4 v = *(const float4*)(g_q + (row0 + r) * Hn + c4);
        float vv[4] = {v.x, v.y, v.z, v.w};
        #pragma unroll
        for (int j = 0; j < 4; j++) {
            __nv_bfloat16 h, l;
            split_bf(vv[j], h, l);
            Ah[r * 72 + c4 + j] = h;
            Al[r * 72 + c4 + j] = l;
        }
    }
    #pragma unroll
    for (int i = 0; i < 8; i++) {
        int f = tid + i * 256;
        int d = f >> 4, c4 = (f & 15) << 2;
        float4 v = *(const float4*)(E + (nbase + d) * Hn + c4);
        float vv[4] = {v.x, v.y, v.z, v.w};
        #pragma unroll
        for (int j = 0; j < 4; j++) {
            __nv_bfloat16 h, l;
            split_bf(vv[j], h, l);
            Eh[d * 72 + c4 + j] = h;
            El[d * 72 + c4 + j] = l;
        }
    }
    __syncthreads();

    if (nbase + wn * 32 + 31 < dmin) return;   // warp-uniform causal skip

    float acc[2][4][4] = {};
    #pragma unroll
    for (int ks = 0; ks < 64; ks += 16) {
        uint32_t ah[2][4], al[2][4], bh[4][2], bl[4][2];
        #pragma unroll
        for (int mi = 0; mi < 2; mi++) {
            int r = wm * 32 + mi * 16 + g;
            int b0 = r * 72 + ks + l2 * 2;
            ah[mi][0] = *(const uint32_t*)&Ah[b0];
            ah[mi][1] = *(const uint32_t*)&Ah[b0 + 8 * 72];
            ah[mi][2] = *(const uint32_t*)&Ah[b0 + 8];
            ah[mi][3] = *(const uint32_t*)&Ah[b0 + 8 * 72 + 8];
            al[mi][0] = *(const uint32_t*)&Al[b0];
            al[mi][1] = *(const uint32_t*)&Al[b0 + 8 * 72];
            al[mi][2] = *(const uint32_t*)&Al[b0 + 8];
            al[mi][3] = *(const uint32_t*)&Al[b0 + 8 * 72 + 8];
        }
        #pragma unroll
        for (int ni = 0; ni < 4; ni++) {
            int n = wn * 32 + ni * 8 + g;
            int b0 = n * 72 + ks + l2 * 2;
            bh[ni][0] = *(const uint32_t*)&Eh[b0];
            bh[ni][1] = *(const uint32_t*)&Eh[b0 + 8];
            bl[ni][0] = *(const uint32_t*)&El[b0];
            bl[ni][1] = *(const uint32_t*)&El[b0 + 8];
        }
        #pragma unroll
        for (int mi = 0; mi < 2; mi++)
            #pragma unroll
            for (int ni = 0; ni < 4; ni++) {
                mma_bf16(acc[mi][ni], ah[mi], bh[ni]);
                mma_bf16(acc[mi][ni], ah[mi], bl[ni]);
                mma_bf16(acc[mi][ni], al[mi], bh[ni]);
            }
    }

    #pragma unroll
    for (int mi = 0; mi < 2; mi++) {
        int rr = row0 + wm * 32 + mi * 16 + g;
        int t1 = rr & 255, t2 = (rr + 8) & 255;
        #pragma unroll
        for (int ni = 0; ni < 4; ni++) {
            int c = nbase + wn * 32 + ni * 8 + l2 * 2;
            if (c + 1 >= 255 - t1) {
                float2 o = {acc[mi][ni][0], acc[mi][ni][1]};
                *(float2*)(g_p + (long)rr * 256 + c) = o;
            }
            if (c + 1 >= 255 - t2) {
                float2 o = {acc[mi][ni][2], acc[mi][ni][3]};
                *(float2*)(g_p + (long)(rr + 8) * 256 + c) = o;
            }
        }
    }
}

// ---------------------------------------------------------------------------
// Kernel 3: attention (unchanged from best passing R2). grid=(256,4), block=256.
// ---------------------------------------------------------------------------
__device__ __forceinline__ int swz64(int k, int m) {
    return k * 64 + (m ^ (((k >> 2) & 7) << 2));
}

__global__ __launch_bounds__(256) void attn_kernel(float* __restrict__ out)
{
    extern __shared__ float smf[];
    float (*sc)[257] = (float(*)[257])smf;
    float* qs = smf + 64 * 257;
    float* kv = qs + 64 * 64;
    float (*vs)[68] = (float(*)[68])kv;

    const int b  = blockIdx.x;
    const int tt = blockIdx.y;
    const int t0 = tt * 64;
    const int tid = threadIdx.x;
    const int w = tid >> 5, l = tid & 31;
    const int wm = w >> 2, wn = w & 3;
    const int lm = l >> 2, ln = l & 3;
    const int m0 = wm * 32 + lm * 4;
    const int n0 = wn * 16 + ln * 4;

    for (int i = tid; i < 64 * 257; i += 256) smf[i] = -1e30f;

    #pragma unroll
    for (int i = 0; i < 4; i++) {
        int f = tid + i * 256;
        int r = f >> 4, h4 = (f & 15) << 2;
        float4 vq = *(const float4*)(g_q + ((long)(b * Tn + t0 + r)) * Hn + h4);
        qs[swz64(h4 + 0, r)] = vq.x;
        qs[swz64(h4 + 1, r)] = vq.y;
        qs[swz64(h4 + 2, r)] = vq.z;
        qs[swz64(h4 + 3, r)] = vq.w;
    }
    __syncthreads();

    for (int st = 0; st <= tt; st++) {
        #pragma unroll
        for (int i = 0; i < 4; i++) {
            int f = tid + i * 256;
            int r = f >> 4, h4 = (f & 15) << 2;
            float4 vk = *(const float4*)(g_k + ((long)(b * Tn + st * 64 + r)) * Hn + h4);
            kv[swz64(h4 + 0, r)] = vk.x;
            kv[swz64(h4 + 1, r)] = vk.y;
            kv[swz64(h4 + 2, r)] = vk.z;
            kv[swz64(h4 + 3, r)] = vk.w;
        }
        __syncthreads();

        float acc[4][4] = {};
        #pragma unroll 8
        for (int kk = 0; kk < 64; kk++) {
            float4 a  = *(const float4*)(qs + swz64(kk, m0));
            float4 bq = *(const float4*)(kv + swz64(kk, n0));
            float av[4] = {a.x, a.y, a.z, a.w};
            float bv[4] = {bq.x, bq.y, bq.z, bq.w};
            #pragma unroll
            for (int i = 0; i < 4; i++)
                #pragma unroll
                for (int j = 0; j < 4; j++)
                    acc[i][j] += av[i] * bv[j];
        }

        #pragma unroll
        for (int i = 0; i < 4; i++) {
            int t = t0 + m0 + i;
            const float* prow = g_p + ((long)(b * Tn + t)) * 256;
            #pragma unroll
            for (int j = 0; j < 4; j++) {
                int s = st * 64 + n0 + j;
                float val = -1e30f;
                if (s <= t) val = acc[i][j] + prow[s - t + 255];
                sc[m0 + i][s] = val;
            }
        }
        __syncthreads();
    }

    {
        const int warp = tid >> 5, lane = tid & 31;
        for (int r = warp * 8; r < warp * 8 + 8; r++) {
            float m = -1e30f;
            #pragma unroll
            for (int s = lane; s < 256; s += 32) m = fmaxf(m, sc[r][s]);
            #pragma unroll
            for (int o = 16; o; o >>= 1) m = fmaxf(m, __shfl_xor_sync(0xffffffffu, m, o));
            float sum = 0.f;
            #pragma unroll
            for (int s = lane; s < 256; s += 32) {
                float e = __expf(sc[r][s] - m);
                sc[r][s] = e;
                sum += e;
            }
            #pragma unroll
            for (int o = 16; o; o >>= 1) sum += __shfl_xor_sync(0xffffffffu, sum, o);
            float inv = 1.0f / sum;
            #pragma unroll
            for (int s = lane; s < 256; s += 32) sc[r][s] *= inv;
        }
    }
    __syncthreads();

    float oacc[4][4] = {};
    for (int st = 0; st <= tt; st++) {
        #pragma unroll
        for (int i = 0; i < 4; i++) {
            int f = tid + i * 256;
            int r = f >> 4, h4 = (f & 15) << 2;
            *(float4*)&vs[r][h4] =
                *(const float4*)(g_v + ((long)(b * Tn + st * 64 + r)) * Hn + h4);
        }
        __syncthreads();

        #pragma unroll 8
        for (int s = 0; s < 64; s++) {
            float4 vv = *(const float4*)&vs[s][n0];
            float bv[4] = {vv.x, vv.y, vv.z, vv.w};
            #pragma unroll
            for (int i = 0; i < 4; i++) {
                float wgt = sc[m0 + i][st * 64 + s];
                #pragma unroll
                for (int j = 0; j < 4; j++)
                    oacc[i][j] += wgt * bv[j];
            }
        }
        __syncthreads();
    }

    #pragma unroll
    for (int i = 0; i < 4; i++) {
        float4 o = {oacc[i][0], oacc[i][1], oacc[i][2], oacc[i][3]};
        *(float4*)(out + ((long)(b * Tn + t0 + m0 + i)) * Hn + n0) = o;
    }
}

// ---------------------------------------------------------------------------
extern "C" void kernel_launch(void* const* d_in, const int* in_sizes, int n_in,
                              void* d_out, int out_size)
{
    const float* x  = (const float*)d_in[0];
    const float* Wk = (const float*)d_in[1];
    const float* Wq = (const float*)d_in[2];
    const float* Wv = (const float*)d_in[3];
    const float* E  = (const float*)d_in[4];
    float* out = (float*)d_out;

    qkv_kernel<<<dim3(Bn * Tn / 128, 3), 256>>>(x, Wq, Wk, Wv);

    const int pos_sm = (2 * 64 * 72 + 2 * 128 * 72) * (int)sizeof(__nv_bfloat16); // 55296
    cudaFuncSetAttribute(pos_kernel, cudaFuncAttributeMaxDynamicSharedMemorySize, pos_sm);
    pos_kernel<<<dim3(Bn * Tn / 64, 2), 256, pos_sm>>>(E);

    const int attn_sm = (64 * 257 + 64 * 64 + 64 * 68) * (int)sizeof(float); // 99584
    cudaFuncSetAttribute(attn_kernel, cudaFuncAttributeMaxDynamicSharedMemorySize, attn_sm);
    attn_kernel<<<dim3(Bn, Tn / 64), 256, attn_sm>>>(out);
}

// round 5
// speedup vs baseline: 1.6780x; 1.2873x over previous
#include <cuda_runtime.h>
#include <cuda_bf16.h>
#include <cstdint>

#define Bn 256
#define Tn 256
#define Cn 256
#define Hn 64

// ---------------- scratch ----------------
__device__ float g_q[Bn*Tn*Hn];
__device__ float g_k[Bn*Tn*Hn];    // k * (1/8), scale folded into W image
__device__ float g_v[Bn*Tn*Hn];
__device__ float g_p[Bn*Tn*256];   // P[b,t,d] = q[b,t].E[d]
// pre-split, pad-72 bf16 operand images ([n][72] per K-chunk; pads zeroed)
__device__ __align__(16) __nv_bfloat16 g_Wh[4*192*72];  // [kt][n=192][72]
__device__ __align__(16) __nv_bfloat16 g_Wl[4*192*72];
__device__ __align__(16) __nv_bfloat16 g_Eh[256*72];    // [d][72]
__device__ __align__(16) __nv_bfloat16 g_El[256*72];

// ---------------- helpers ----------------
__device__ __forceinline__ uint32_t smem_u32(const void* p) {
    uint32_t a;
    asm("{ .reg .u64 t; cvta.to.shared.u64 t, %1; cvt.u32.u64 %0, t; }" : "=r"(a) : "l"(p));
    return a;
}
__device__ __forceinline__ void mma_bf16(float* c, const uint32_t* a, const uint32_t* b) {
    asm volatile(
        "mma.sync.aligned.m16n8k16.row.col.f32.bf16.bf16.f32 "
        "{%0,%1,%2,%3}, {%4,%5,%6,%7}, {%8,%9}, {%0,%1,%2,%3};"
        : "+f"(c[0]), "+f"(c[1]), "+f"(c[2]), "+f"(c[3])
        : "r"(a[0]), "r"(a[1]), "r"(a[2]), "r"(a[3]), "r"(b[0]), "r"(b[1]));
}
__device__ __forceinline__ void ldsm4(uint32_t* r, uint32_t addr) {
    asm volatile("ldmatrix.sync.aligned.m8n8.x4.shared.b16 {%0,%1,%2,%3}, [%4];"
        : "=r"(r[0]), "=r"(r[1]), "=r"(r[2]), "=r"(r[3]) : "r"(addr));
}
__device__ __forceinline__ void split_bf(float v, __nv_bfloat16& h, __nv_bfloat16& l) {
    h = __float2bfloat16(v);
    l = __float2bfloat16(v - __bfloat162float(h));
}
__device__ __forceinline__ uint32_t pk(__nv_bfloat16 a, __nv_bfloat16 b) {
    return (uint32_t)__bfloat16_as_ushort(a) | ((uint32_t)__bfloat16_as_ushort(b) << 16);
}

// ---------------------------------------------------------------------------
// Setup: build hi/lo pad-72 images of [Wq|Wk*0.125|Wv] and E. 288x256 threads.
// ---------------------------------------------------------------------------
__global__ __launch_bounds__(256) void setup_kernel(
    const float* __restrict__ Wk, const float* __restrict__ Wq,
    const float* __restrict__ Wv, const float* __restrict__ E)
{
    int id = blockIdx.x * 256 + threadIdx.x;
    if (id < 4 * 192 * 72) {
        int kt = id / (192 * 72);
        int rem = id % (192 * 72);
        int n = rem / 72, k = rem % 72;
        float v = 0.f;
        if (k < 64) {
            int which = n >> 6, col = n & 63;
            const float* W = (which == 0) ? Wq : (which == 1) ? Wk : Wv;
            v = W[(kt * 64 + k) * Hn + col];
            if (which == 1) v *= 0.125f;
        }
        __nv_bfloat16 h, l;
        split_bf(v, h, l);
        g_Wh[id] = h;
        g_Wl[id] = l;
    } else {
        int id2 = id - 4 * 192 * 72;
        if (id2 < 256 * 72) {
            int d = id2 / 72, k = id2 % 72;
            float v = (k < 64) ? E[d * Hn + k] : 0.f;
            __nv_bfloat16 h, l;
            split_bf(v, h, l);
            g_Eh[id2] = h;
            g_El[id2] = l;
        }
    }
}

// ---------------------------------------------------------------------------
// Fused qkv: one 65536x256 @ 256x192 GEMM (bf16x3). grid=512, block=512.
// Block tile 128m x 192n, K chunks of 64. Warps 4m x 4n -> 32x48 each.
// A split in-kernel -> smem [128][72] hi/lo; B chunk = uint4 copy of image.
// ---------------------------------------------------------------------------
__global__ __launch_bounds__(512) void qkv_kernel(const float* __restrict__ x)
{
    extern __shared__ __nv_bfloat16 smb[];
    __nv_bfloat16* Ah = smb;                 // 128*72
    __nv_bfloat16* Al = Ah + 128 * 72;
    __nv_bfloat16* Bh = Al + 128 * 72;       // 192*72
    __nv_bfloat16* Bl = Bh + 192 * 72;

    const int row0 = blockIdx.x * 128;
    const int tid = threadIdx.x, w = tid >> 5, lane = tid & 31;
    const int wm = w >> 2, wn = w & 3;
    const int g = lane >> 2, l2 = lane & 3;

    const uint32_t aH = smem_u32(Ah), aL = smem_u32(Al);
    const uint32_t bH = smem_u32(Bh), bL = smem_u32(Bl);
    // per-thread ldmatrix row/col offsets
    const int arow = wm * 32 + (lane & 15);
    const int acol = (lane >> 4) * 8;
    const int brow = wn * 48 + (lane & 7) + (lane >> 4) * 8;
    const int bcol = ((lane >> 3) & 1) * 8;

    float acc[2][6][4] = {};

    for (int ct = 0; ct < 4; ct++) {
        float4 xv[4];
        #pragma unroll
        for (int i = 0; i < 4; i++) {
            int f = tid + i * 512;
            int r = f >> 4, c4 = (f & 15) << 2;
            xv[i] = *(const float4*)(x + (row0 + r) * Cn + ct * 64 + c4);
        }
        __syncthreads();   // previous chunk's ldmatrix reads done

        #pragma unroll
        for (int i = 0; i < 4; i++) {
            int f = tid + i * 512;
            int r = f >> 4, c4 = (f & 15) << 2;
            __nv_bfloat16 h0, l0, h1, l1, h2, l2b, h3, l3;
            split_bf(xv[i].x, h0, l0);
            split_bf(xv[i].y, h1, l1);
            split_bf(xv[i].z, h2, l2b);
            split_bf(xv[i].w, h3, l3);
            uint2 uh = {pk(h0, h1), pk(h2, h3)};
            uint2 ul = {pk(l0, l1), pk(l2b, l3)};
            *(uint2*)(Ah + r * 72 + c4) = uh;
            *(uint2*)(Al + r * 72 + c4) = ul;
        }
        {
            uint4* dh = (uint4*)Bh;
            uint4* dl = (uint4*)Bl;
            const uint4* sh = (const uint4*)(g_Wh + ct * 192 * 72);
            const uint4* sl = (const uint4*)(g_Wl + ct * 192 * 72);
            #pragma unroll
            for (int idx = tid; idx < 1728; idx += 512) {
                dh[idx] = sh[idx];
                dl[idx] = sl[idx];
            }
        }
        __syncthreads();

        #pragma unroll
        for (int ks = 0; ks < 64; ks += 16) {
            uint32_t ah[2][4], al[2][4], bh[3][4], bl[3][4];
            #pragma unroll
            for (int mi = 0; mi < 2; mi++) {
                uint32_t off = ((arow + mi * 16) * 72 + ks + acol) * 2;
                ldsm4(ah[mi], aH + off);
                ldsm4(al[mi], aL + off);
            }
            #pragma unroll
            for (int nj = 0; nj < 3; nj++) {
                uint32_t off = ((brow + nj * 16) * 72 + ks + bcol) * 2;
                ldsm4(bh[nj], bH + off);
                ldsm4(bl[nj], bL + off);
            }
            #pragma unroll
            for (int mi = 0; mi < 2; mi++)
                #pragma unroll
                for (int ni = 0; ni < 6; ni++) {
                    const uint32_t* ph = &bh[ni >> 1][(ni & 1) * 2];
                    const uint32_t* pl = &bl[ni >> 1][(ni & 1) * 2];
                    mma_bf16(acc[mi][ni], ah[mi], ph);
                    mma_bf16(acc[mi][ni], ah[mi], pl);
                    mma_bf16(acc[mi][ni], al[mi], ph);
                }
        }
    }

    #pragma unroll
    for (int mi = 0; mi < 2; mi++) {
        int rr = row0 + wm * 32 + mi * 16 + g;
        #pragma unroll
        for (int ni = 0; ni < 6; ni++) {
            int n = wn * 48 + ni * 8 + l2 * 2;
            float* outp = (n < 64) ? g_q : (n < 128) ? g_k : g_v;
            int col = n & 63;
            float2 o0 = {acc[mi][ni][0], acc[mi][ni][1]};
            float2 o1 = {acc[mi][ni][2], acc[mi][ni][3]};
            *(float2*)(outp + rr * Hn + col) = o0;
            *(float2*)(outp + (rr + 8) * Hn + col) = o1;
        }
    }
}

// ---------------------------------------------------------------------------
// pos: P = q @ E^T (bf16x3, ldmatrix). grid=(1024,2), block=256.
// Block tile 64m x 128n, K=64. Warps 2m x 4n -> 32x32. Causal skips kept.
// ---------------------------------------------------------------------------
__global__ __launch_bounds__(256) void pos_kernel()
{
    const int row0  = blockIdx.x * 64;
    const int t0    = row0 & 255;
    const int nbase = blockIdx.y * 128;
    const int dmin  = 192 - t0;
    if (nbase + 127 < dmin) return;

    extern __shared__ __nv_bfloat16 smb[];
    __nv_bfloat16* Ah = smb;                 // 64*72
    __nv_bfloat16* Al = Ah + 64 * 72;
    __nv_bfloat16* Eh = Al + 64 * 72;        // 128*72
    __nv_bfloat16* El = Eh + 128 * 72;

    const int tid = threadIdx.x, w = tid >> 5, lane = tid & 31;
    const int wm = w >> 2, wn = w & 3;
    const int g = lane >> 2, l2 = lane & 3;

    #pragma unroll
    for (int i = 0; i < 4; i++) {
        int f = tid + i * 256;
        int r = f >> 4, c4 = (f & 15) << 2;
        float4 v = *(const float4*)(g_q + (row0 + r) * Hn + c4);
        __nv_bfloat16 h0, l0, h1, l1, h2, l2b, h3, l3;
        split_bf(v.x, h0, l0);
        split_bf(v.y, h1, l1);
        split_bf(v.z, h2, l2b);
        split_bf(v.w, h3, l3);
        uint2 uh = {pk(h0, h1), pk(h2, h3)};
        uint2 ul = {pk(l0, l1), pk(l2b, l3)};
        *(uint2*)(Ah + r * 72 + c4) = uh;
        *(uint2*)(Al + r * 72 + c4) = ul;
    }
    {
        uint4* dh = (uint4*)Eh;
        uint4* dl = (uint4*)El;
        const uint4* sh = (const uint4*)(g_Eh + nbase * 72);
        const uint4* sl = (const uint4*)(g_El + nbase * 72);
        #pragma unroll
        for (int idx = tid; idx < 1152; idx += 256) {
            dh[idx] = sh[idx];
            dl[idx] = sl[idx];
        }
    }
    __syncthreads();

    if (nbase + wn * 32 + 31 < dmin) return;   // warp-uniform causal skip

    const uint32_t aH = smem_u32(Ah), aL = smem_u32(Al);
    const uint32_t bH = smem_u32(Eh), bL = smem_u32(El);
    const int arow = wm * 32 + (lane & 15);
    const int acol = (lane >> 4) * 8;
    const int brow = wn * 32 + (lane & 7) + (lane >> 4) * 8;
    const int bcol = ((lane >> 3) & 1) * 8;

    float acc[2][4][4] = {};
    #pragma unroll
    for (int ks = 0; ks < 64; ks += 16) {
        uint32_t ah[2][4], al[2][4], bh[2][4], bl[2][4];
        #pragma unroll
        for (int mi = 0; mi < 2; mi++) {
            uint32_t off = ((arow + mi * 16) * 72 + ks + acol) * 2;
            ldsm4(ah[mi], aH + off);
            ldsm4(al[mi], aL + off);
        }
        #pragma unroll
        for (int nj = 0; nj < 2; nj++) {
            uint32_t off = ((brow + nj * 16) * 72 + ks + bcol) * 2;
            ldsm4(bh[nj], bH + off);
            ldsm4(bl[nj], bL + off);
        }
        #pragma unroll
        for (int mi = 0; mi < 2; mi++)
            #pragma unroll
            for (int ni = 0; ni < 4; ni++) {
                const uint32_t* ph = &bh[ni >> 1][(ni & 1) * 2];
                const uint32_t* pl = &bl[ni >> 1][(ni & 1) * 2];
                mma_bf16(acc[mi][ni], ah[mi], ph);
                mma_bf16(acc[mi][ni], ah[mi], pl);
                mma_bf16(acc[mi][ni], al[mi], ph);
            }
    }

    #pragma unroll
    for (int mi = 0; mi < 2; mi++) {
        int rr = row0 + wm * 32 + mi * 16 + g;
        int t1 = rr & 255, t2 = (rr + 8) & 255;
        #pragma unroll
        for (int ni = 0; ni < 4; ni++) {
            int c = nbase + wn * 32 + ni * 8 + l2 * 2;
            if (c + 1 >= 255 - t1) {
                float2 o = {acc[mi][ni][0], acc[mi][ni][1]};
                *(float2*)(g_p + (long)rr * 256 + c) = o;
            }
            if (c + 1 >= 255 - t2) {
                float2 o = {acc[mi][ni][2], acc[mi][ni][3]};
                *(float2*)(g_p + (long)(rr + 8) * 256 + c) = o;
            }
        }
    }
}

// ---------------------------------------------------------------------------
// attention (unchanged, passing). grid=(256,4), block=256.
// ---------------------------------------------------------------------------
__device__ __forceinline__ int swz64(int k, int m) {
    return k * 64 + (m ^ (((k >> 2) & 7) << 2));
}

__global__ __launch_bounds__(256) void attn_kernel(float* __restrict__ out)
{
    extern __shared__ float smf[];
    float (*sc)[257] = (float(*)[257])smf;
    float* qs = smf + 64 * 257;
    float* kv = qs + 64 * 64;
    float (*vs)[68] = (float(*)[68])kv;

    const int b  = blockIdx.x;
    const int tt = blockIdx.y;
    const int t0 = tt * 64;
    const int tid = threadIdx.x;
    const int w = tid >> 5, l = tid & 31;
    const int wm = w >> 2, wn = w & 3;
    const int lm = l >> 2, ln = l & 3;
    const int m0 = wm * 32 + lm * 4;
    const int n0 = wn * 16 + ln * 4;

    for (int i = tid; i < 64 * 257; i += 256) smf[i] = -1e30f;

    #pragma unroll
    for (int i = 0; i < 4; i++) {
        int f = tid + i * 256;
        int r = f >> 4, h4 = (f & 15) << 2;
        float4 vq = *(const float4*)(g_q + ((long)(b * Tn + t0 + r)) * Hn + h4);
        qs[swz64(h4 + 0, r)] = vq.x;
        qs[swz64(h4 + 1, r)] = vq.y;
        qs[swz64(h4 + 2, r)] = vq.z;
        qs[swz64(h4 + 3, r)] = vq.w;
    }
    __syncthreads();

    for (int st = 0; st <= tt; st++) {
        #pragma unroll
        for (int i = 0; i < 4; i++) {
            int f = tid + i * 256;
            int r = f >> 4, h4 = (f & 15) << 2;
            float4 vk = *(const float4*)(g_k + ((long)(b * Tn + st * 64 + r)) * Hn + h4);
            kv[swz64(h4 + 0, r)] = vk.x;
            kv[swz64(h4 + 1, r)] = vk.y;
            kv[swz64(h4 + 2, r)] = vk.z;
            kv[swz64(h4 + 3, r)] = vk.w;
        }
        __syncthreads();

        float acc[4][4] = {};
        #pragma unroll 8
        for (int kk = 0; kk < 64; kk++) {
            float4 a  = *(const float4*)(qs + swz64(kk, m0));
            float4 bq = *(const float4*)(kv + swz64(kk, n0));
            float av[4] = {a.x, a.y, a.z, a.w};
            float bv[4] = {bq.x, bq.y, bq.z, bq.w};
            #pragma unroll
            for (int i = 0; i < 4; i++)
                #pragma unroll
                for (int j = 0; j < 4; j++)
                    acc[i][j] += av[i] * bv[j];
        }

        #pragma unroll
        for (int i = 0; i < 4; i++) {
            int t = t0 + m0 + i;
            const float* prow = g_p + ((long)(b * Tn + t)) * 256;
            #pragma unroll
            for (int j = 0; j < 4; j++) {
                int s = st * 64 + n0 + j;
                float val = -1e30f;
                if (s <= t) val = acc[i][j] + prow[s - t + 255];
                sc[m0 + i][s] = val;
            }
        }
        __syncthreads();
    }

    {
        const int warp = tid >> 5, lane = tid & 31;
        for (int r = warp * 8; r < warp * 8 + 8; r++) {
            float m = -1e30f;
            #pragma unroll
            for (int s = lane; s < 256; s += 32) m = fmaxf(m, sc[r][s]);
            #pragma unroll
            for (int o = 16; o; o >>= 1) m = fmaxf(m, __shfl_xor_sync(0xffffffffu, m, o));
            float sum = 0.f;
            #pragma unroll
            for (int s = lane; s < 256; s += 32) {
                float e = __expf(sc[r][s] - m);
                sc[r][s] = e;
                sum += e;
            }
            #pragma unroll
            for (int o = 16; o; o >>= 1) sum += __shfl_xor_sync(0xffffffffu, sum, o);
            float inv = 1.0f / sum;
            #pragma unroll
            for (int s = lane; s < 256; s += 32) sc[r][s] *= inv;
        }
    }
    __syncthreads();

    float oacc[4][4] = {};
    for (int st = 0; st <= tt; st++) {
        #pragma unroll
        for (int i = 0; i < 4; i++) {
            int f = tid + i * 256;
            int r = f >> 4, h4 = (f & 15) << 2;
            *(float4*)&vs[r][h4] =
                *(const float4*)(g_v + ((long)(b * Tn + st * 64 + r)) * Hn + h4);
        }
        __syncthreads();

        #pragma unroll 8
        for (int s = 0; s < 64; s++) {
            float4 vv = *(const float4*)&vs[s][n0];
            float bv[4] = {vv.x, vv.y, vv.z, vv.w};
            #pragma unroll
            for (int i = 0; i < 4; i++) {
                float wgt = sc[m0 + i][st * 64 + s];
                #pragma unroll
                for (int j = 0; j < 4; j++)
                    oacc[i][j] += wgt * bv[j];
            }
        }
        __syncthreads();
    }

    #pragma unroll
    for (int i = 0; i < 4; i++) {
        float4 o = {oacc[i][0], oacc[i][1], oacc[i][2], oacc[i][3]};
        *(float4*)(out + ((long)(b * Tn + t0 + m0 + i)) * Hn + n0) = o;
    }
}

// ---------------------------------------------------------------------------
extern "C" void kernel_launch(void* const* d_in, const int* in_sizes, int n_in,
                              void* d_out, int out_size)
{
    const float* x  = (const float*)d_in[0];
    const float* Wk = (const float*)d_in[1];
    const float* Wq = (const float*)d_in[2];
    const float* Wv = (const float*)d_in[3];
    const float* E  = (const float*)d_in[4];
    float* out = (float*)d_out;

    setup_kernel<<<288, 256>>>(Wk, Wq, Wv, E);

    const int qkv_sm = (2 * 128 * 72 + 2 * 192 * 72) * (int)sizeof(__nv_bfloat16); // 92160
    cudaFuncSetAttribute(qkv_kernel, cudaFuncAttributeMaxDynamicSharedMemorySize, qkv_sm);
    qkv_kernel<<<Bn * Tn / 128, 512, qkv_sm>>>(x);

    const int pos_sm = (2 * 64 * 72 + 2 * 128 * 72) * (int)sizeof(__nv_bfloat16);  // 55296
    cudaFuncSetAttribute(pos_kernel, cudaFuncAttributeMaxDynamicSharedMemorySize, pos_sm);
    pos_kernel<<<dim3(Bn * Tn / 64, 2), 256, pos_sm>>>();

    const int attn_sm = (64 * 257 + 64 * 64 + 64 * 68) * (int)sizeof(float); // 99584
    cudaFuncSetAttribute(attn_kernel, cudaFuncAttributeMaxDynamicSharedMemorySize, attn_sm);
    attn_kernel<<<dim3(Bn, Tn / 64), 256, attn_sm>>>(out);
}

// round 6
// speedup vs baseline: 1.7764x; 1.0587x over previous
#include <cuda_runtime.h>
#include <cuda_bf16.h>
#include <cstdint>

#define Bn 256
#define Tn 256
#define Cn 256
#define Hn 64

// ---------------- scratch ----------------
__device__ float g_q[Bn*Tn*Hn];
__device__ float g_k[Bn*Tn*Hn];    // k * (1/8), scale folded into W image
__device__ float g_v[Bn*Tn*Hn];
__device__ float g_p[Bn*Tn*256];   // P[b,t,d] = q[b,t].E[d]
// pre-split, pad-72 bf16 operand images ([n][72] per K-chunk; pads zeroed)
__device__ __align__(16) __nv_bfloat16 g_Wh[4*192*72];  // [kt][n=192][72]
__device__ __align__(16) __nv_bfloat16 g_Wl[4*192*72];
__device__ __align__(16) __nv_bfloat16 g_Eh[256*72];    // [d][72]
__device__ __align__(16) __nv_bfloat16 g_El[256*72];

// ---------------- helpers ----------------
__device__ __forceinline__ uint32_t smem_u32(const void* p) {
    uint32_t a;
    asm("{ .reg .u64 t; cvta.to.shared.u64 t, %1; cvt.u32.u64 %0, t; }" : "=r"(a) : "l"(p));
    return a;
}
__device__ __forceinline__ void mma_bf16(float* c, const uint32_t* a, const uint32_t* b) {
    asm volatile(
        "mma.sync.aligned.m16n8k16.row.col.f32.bf16.bf16.f32 "
        "{%0,%1,%2,%3}, {%4,%5,%6,%7}, {%8,%9}, {%0,%1,%2,%3};"
        : "+f"(c[0]), "+f"(c[1]), "+f"(c[2]), "+f"(c[3])
        : "r"(a[0]), "r"(a[1]), "r"(a[2]), "r"(a[3]), "r"(b[0]), "r"(b[1]));
}
__device__ __forceinline__ void ldsm4(uint32_t* r, uint32_t addr) {
    asm volatile("ldmatrix.sync.aligned.m8n8.x4.shared.b16 {%0,%1,%2,%3}, [%4];"
        : "=r"(r[0]), "=r"(r[1]), "=r"(r[2]), "=r"(r[3]) : "r"(addr));
}
__device__ __forceinline__ void ldsm4t(uint32_t* r, uint32_t addr) {
    asm volatile("ldmatrix.sync.aligned.m8n8.x4.trans.shared.b16 {%0,%1,%2,%3}, [%4];"
        : "=r"(r[0]), "=r"(r[1]), "=r"(r[2]), "=r"(r[3]) : "r"(addr));
}
__device__ __forceinline__ void split_bf(float v, __nv_bfloat16& h, __nv_bfloat16& l) {
    h = __float2bfloat16(v);
    l = __float2bfloat16(v - __bfloat162float(h));
}
__device__ __forceinline__ uint32_t pk(__nv_bfloat16 a, __nv_bfloat16 b) {
    return (uint32_t)__bfloat16_as_ushort(a) | ((uint32_t)__bfloat16_as_ushort(b) << 16);
}

// ---------------------------------------------------------------------------
// Setup: build hi/lo pad-72 images of [Wq|Wk*0.125|Wv] and E.
// ---------------------------------------------------------------------------
__global__ __launch_bounds__(256) void setup_kernel(
    const float* __restrict__ Wk, const float* __restrict__ Wq,
    const float* __restrict__ Wv, const float* __restrict__ E)
{
    int id = blockIdx.x * 256 + threadIdx.x;
    if (id < 4 * 192 * 72) {
        int kt = id / (192 * 72);
        int rem = id % (192 * 72);
        int n = rem / 72, k = rem % 72;
        float v = 0.f;
        if (k < 64) {
            int which = n >> 6, col = n & 63;
            const float* W = (which == 0) ? Wq : (which == 1) ? Wk : Wv;
            v = W[(kt * 64 + k) * Hn + col];
            if (which == 1) v *= 0.125f;
        }
        __nv_bfloat16 h, l;
        split_bf(v, h, l);
        g_Wh[id] = h;
        g_Wl[id] = l;
    } else {
        int id2 = id - 4 * 192 * 72;
        if (id2 < 256 * 72) {
            int d = id2 / 72, k = id2 % 72;
            float v = (k < 64) ? E[d * Hn + k] : 0.f;
            __nv_bfloat16 h, l;
            split_bf(v, h, l);
            g_Eh[id2] = h;
            g_El[id2] = l;
        }
    }
}

// ---------------------------------------------------------------------------
// Fused qkv GEMM (bf16x3, ldmatrix). grid=512, block=512. (unchanged, R5)
// ---------------------------------------------------------------------------
__global__ __launch_bounds__(512) void qkv_kernel(const float* __restrict__ x)
{
    extern __shared__ __nv_bfloat16 smb[];
    __nv_bfloat16* Ah = smb;
    __nv_bfloat16* Al = Ah + 128 * 72;
    __nv_bfloat16* Bh = Al + 128 * 72;
    __nv_bfloat16* Bl = Bh + 192 * 72;

    const int row0 = blockIdx.x * 128;
    const int tid = threadIdx.x, w = tid >> 5, lane = tid & 31;
    const int wm = w >> 2, wn = w & 3;
    const int g = lane >> 2, l2 = lane & 3;

    const uint32_t aH = smem_u32(Ah), aL = smem_u32(Al);
    const uint32_t bH = smem_u32(Bh), bL = smem_u32(Bl);
    const int arow = wm * 32 + (lane & 15);
    const int acol = (lane >> 4) * 8;
    const int brow = wn * 48 + (lane & 7) + (lane >> 4) * 8;
    const int bcol = ((lane >> 3) & 1) * 8;

    float acc[2][6][4] = {};

    for (int ct = 0; ct < 4; ct++) {
        float4 xv[4];
        #pragma unroll
        for (int i = 0; i < 4; i++) {
            int f = tid + i * 512;
            int r = f >> 4, c4 = (f & 15) << 2;
            xv[i] = *(const float4*)(x + (row0 + r) * Cn + ct * 64 + c4);
        }
        __syncthreads();

        #pragma unroll
        for (int i = 0; i < 4; i++) {
            int f = tid + i * 512;
            int r = f >> 4, c4 = (f & 15) << 2;
            __nv_bfloat16 h0, l0, h1, l1, h2, l2b, h3, l3;
            split_bf(xv[i].x, h0, l0);
            split_bf(xv[i].y, h1, l1);
            split_bf(xv[i].z, h2, l2b);
            split_bf(xv[i].w, h3, l3);
            uint2 uh = {pk(h0, h1), pk(h2, h3)};
            uint2 ul = {pk(l0, l1), pk(l2b, l3)};
            *(uint2*)(Ah + r * 72 + c4) = uh;
            *(uint2*)(Al + r * 72 + c4) = ul;
        }
        {
            uint4* dh = (uint4*)Bh;
            uint4* dl = (uint4*)Bl;
            const uint4* sh = (const uint4*)(g_Wh + ct * 192 * 72);
            const uint4* sl = (const uint4*)(g_Wl + ct * 192 * 72);
            #pragma unroll
            for (int idx = tid; idx < 1728; idx += 512) {
                dh[idx] = sh[idx];
                dl[idx] = sl[idx];
            }
        }
        __syncthreads();

        #pragma unroll
        for (int ks = 0; ks < 64; ks += 16) {
            uint32_t ah[2][4], al[2][4], bh[3][4], bl[3][4];
            #pragma unroll
            for (int mi = 0; mi < 2; mi++) {
                uint32_t off = ((arow + mi * 16) * 72 + ks + acol) * 2;
                ldsm4(ah[mi], aH + off);
                ldsm4(al[mi], aL + off);
            }
            #pragma unroll
            for (int nj = 0; nj < 3; nj++) {
                uint32_t off = ((brow + nj * 16) * 72 + ks + bcol) * 2;
                ldsm4(bh[nj], bH + off);
                ldsm4(bl[nj], bL + off);
            }
            #pragma unroll
            for (int mi = 0; mi < 2; mi++)
                #pragma unroll
                for (int ni = 0; ni < 6; ni++) {
                    const uint32_t* ph = &bh[ni >> 1][(ni & 1) * 2];
                    const uint32_t* pl = &bl[ni >> 1][(ni & 1) * 2];
                    mma_bf16(acc[mi][ni], ah[mi], ph);
                    mma_bf16(acc[mi][ni], ah[mi], pl);
                    mma_bf16(acc[mi][ni], al[mi], ph);
                }
        }
    }

    #pragma unroll
    for (int mi = 0; mi < 2; mi++) {
        int rr = row0 + wm * 32 + mi * 16 + g;
        #pragma unroll
        for (int ni = 0; ni < 6; ni++) {
            int n = wn * 48 + ni * 8 + l2 * 2;
            float* outp = (n < 64) ? g_q : (n < 128) ? g_k : g_v;
            int col = n & 63;
            float2 o0 = {acc[mi][ni][0], acc[mi][ni][1]};
            float2 o1 = {acc[mi][ni][2], acc[mi][ni][3]};
            *(float2*)(outp + rr * Hn + col) = o0;
            *(float2*)(outp + (rr + 8) * Hn + col) = o1;
        }
    }
}

// ---------------------------------------------------------------------------
// pos: P = q @ E^T (bf16x3, ldmatrix). grid=(1024,2), block=256. (unchanged, R5)
// ---------------------------------------------------------------------------
__global__ __launch_bounds__(256) void pos_kernel()
{
    const int row0  = blockIdx.x * 64;
    const int t0    = row0 & 255;
    const int nbase = blockIdx.y * 128;
    const int dmin  = 192 - t0;
    if (nbase + 127 < dmin) return;

    extern __shared__ __nv_bfloat16 smb[];
    __nv_bfloat16* Ah = smb;
    __nv_bfloat16* Al = Ah + 64 * 72;
    __nv_bfloat16* Eh = Al + 64 * 72;
    __nv_bfloat16* El = Eh + 128 * 72;

    const int tid = threadIdx.x, w = tid >> 5, lane = tid & 31;
    const int wm = w >> 2, wn = w & 3;
    const int g = lane >> 2, l2 = lane & 3;

    #pragma unroll
    for (int i = 0; i < 4; i++) {
        int f = tid + i * 256;
        int r = f >> 4, c4 = (f & 15) << 2;
        float4 v = *(const float4*)(g_q + (row0 + r) * Hn + c4);
        __nv_bfloat16 h0, l0, h1, l1, h2, l2b, h3, l3;
        split_bf(v.x, h0, l0);
        split_bf(v.y, h1, l1);
        split_bf(v.z, h2, l2b);
        split_bf(v.w, h3, l3);
        uint2 uh = {pk(h0, h1), pk(h2, h3)};
        uint2 ul = {pk(l0, l1), pk(l2b, l3)};
        *(uint2*)(Ah + r * 72 + c4) = uh;
        *(uint2*)(Al + r * 72 + c4) = ul;
    }
    {
        uint4* dh = (uint4*)Eh;
        uint4* dl = (uint4*)El;
        const uint4* sh = (const uint4*)(g_Eh + nbase * 72);
        const uint4* sl = (const uint4*)(g_El + nbase * 72);
        #pragma unroll
        for (int idx = tid; idx < 1152; idx += 256) {
            dh[idx] = sh[idx];
            dl[idx] = sl[idx];
        }
    }
    __syncthreads();

    if (nbase + wn * 32 + 31 < dmin) return;

    const uint32_t aH = smem_u32(Ah), aL = smem_u32(Al);
    const uint32_t bH = smem_u32(Eh), bL = smem_u32(El);
    const int arow = wm * 32 + (lane & 15);
    const int acol = (lane >> 4) * 8;
    const int brow = wn * 32 + (lane & 7) + (lane >> 4) * 8;
    const int bcol = ((lane >> 3) & 1) * 8;

    float acc[2][4][4] = {};
    #pragma unroll
    for (int ks = 0; ks < 64; ks += 16) {
        uint32_t ah[2][4], al[2][4], bh[2][4], bl[2][4];
        #pragma unroll
        for (int mi = 0; mi < 2; mi++) {
            uint32_t off = ((arow + mi * 16) * 72 + ks + acol) * 2;
            ldsm4(ah[mi], aH + off);
            ldsm4(al[mi], aL + off);
        }
        #pragma unroll
        for (int nj = 0; nj < 2; nj++) {
            uint32_t off = ((brow + nj * 16) * 72 + ks + bcol) * 2;
            ldsm4(bh[nj], bH + off);
            ldsm4(bl[nj], bL + off);
        }
        #pragma unroll
        for (int mi = 0; mi < 2; mi++)
            #pragma unroll
            for (int ni = 0; ni < 4; ni++) {
                const uint32_t* ph = &bh[ni >> 1][(ni & 1) * 2];
                const uint32_t* pl = &bl[ni >> 1][(ni & 1) * 2];
                mma_bf16(acc[mi][ni], ah[mi], ph);
                mma_bf16(acc[mi][ni], ah[mi], pl);
                mma_bf16(acc[mi][ni], al[mi], ph);
            }
    }

    #pragma unroll
    for (int mi = 0; mi < 2; mi++) {
        int rr = row0 + wm * 32 + mi * 16 + g;
        int t1 = rr & 255, t2 = (rr + 8) & 255;
        #pragma unroll
        for (int ni = 0; ni < 4; ni++) {
            int c = nbase + wn * 32 + ni * 8 + l2 * 2;
            if (c + 1 >= 255 - t1) {
                float2 o = {acc[mi][ni][0], acc[mi][ni][1]};
                *(float2*)(g_p + (long)rr * 256 + c) = o;
            }
            if (c + 1 >= 255 - t2) {
                float2 o = {acc[mi][ni][2], acc[mi][ni][3]};
                *(float2*)(g_p + (long)(rr + 8) * 256 + c) = o;
            }
        }
    }
}

// ---------------------------------------------------------------------------
// attention via bf16x3 mma. grid=(256,4), block=256 (8 warps).
// Block = 64 q-rows x 256 keys. Whole live k (then v, same buffers) resident
// in smem; scores fp32 in smem; softmax emits packed bf16 hi/lo weights.
// Warps 2m x 4n: score warp tile 32m x 16n per 64-key st-tile.
// smem: sc f32[64][264] | wh,wl bf16[64][264] | qh,ql bf16[64][72]
//       | kh,kl bf16[256][72]   => 227,328 B
// ---------------------------------------------------------------------------
__global__ __launch_bounds__(256) void attn_kernel(float* __restrict__ out)
{
    extern __shared__ char smc[];
    float* sc = (float*)smc;                                   // 64*264 f32
    __nv_bfloat16* wh = (__nv_bfloat16*)(smc + 64 * 264 * 4);  // 64*264
    __nv_bfloat16* wl = wh + 64 * 264;
    __nv_bfloat16* qh = wl + 64 * 264;                         // 64*72
    __nv_bfloat16* ql = qh + 64 * 72;
    __nv_bfloat16* kh = ql + 64 * 72;                          // 256*72
    __nv_bfloat16* kl = kh + 256 * 72;

    const int b  = blockIdx.x;
    const int tt = blockIdx.y;
    const int t0 = tt * 64;
    const int nst = tt + 1;
    const int send = nst * 64;              // live key extent
    const int tid = threadIdx.x, w = tid >> 5, lane = tid & 31;
    const int wm = w >> 2, wn = w & 3;
    const int g = lane >> 2, l2 = lane & 3;

    const uint32_t qHa = smem_u32(qh), qLa = smem_u32(ql);
    const uint32_t kHa = smem_u32(kh), kLa = smem_u32(kl);
    const uint32_t wHa = smem_u32(wh), wLa = smem_u32(wl);

    // ---- load q tile (64x64) and live k rows, split hi/lo ----
    #pragma unroll
    for (int i = 0; i < 4; i++) {
        int f = tid + i * 256;
        int r = f >> 4, c4 = (f & 15) << 2;
        float4 v = *(const float4*)(g_q + ((long)(b * Tn + t0 + r)) * Hn + c4);
        __nv_bfloat16 h0, l0, h1, l1, h2, l2b, h3, l3;
        split_bf(v.x, h0, l0); split_bf(v.y, h1, l1);
        split_bf(v.z, h2, l2b); split_bf(v.w, h3, l3);
        *(uint2*)(qh + r * 72 + c4) = {pk(h0, h1), pk(h2, h3)};
        *(uint2*)(ql + r * 72 + c4) = {pk(l0, l1), pk(l2b, l3)};
    }
    for (int f = tid; f < send * 16; f += 256) {
        int r = f >> 4, c4 = (f & 15) << 2;
        float4 v = *(const float4*)(g_k + ((long)(b * Tn + r)) * Hn + c4);
        __nv_bfloat16 h0, l0, h1, l1, h2, l2b, h3, l3;
        split_bf(v.x, h0, l0); split_bf(v.y, h1, l1);
        split_bf(v.z, h2, l2b); split_bf(v.w, h3, l3);
        *(uint2*)(kh + r * 72 + c4) = {pk(h0, h1), pk(h2, h3)};
        *(uint2*)(kl + r * 72 + c4) = {pk(l0, l1), pk(l2b, l3)};
    }
    __syncthreads();

    // ---- q A-fragments in registers (reused across all st) ----
    const int arow = wm * 32 + (lane & 15);
    const int acol = (lane >> 4) * 8;
    uint32_t ah[2][4][4], al[2][4][4];
    #pragma unroll
    for (int mi = 0; mi < 2; mi++)
        #pragma unroll
        for (int ks = 0; ks < 4; ks++) {
            uint32_t off = ((arow + mi * 16) * 72 + ks * 16 + acol) * 2;
            ldsm4(ah[mi][ks], qHa + off);
            ldsm4(al[mi][ks], qLa + off);
        }

    // ---- score phase: content + position gather + causal mask ----
    const int brow = wn * 16 + (lane & 7) + (lane >> 4) * 8;
    const int bcol = ((lane >> 3) & 1) * 8;
    for (int st = 0; st < nst; st++) {
        float acc[2][2][4] = {};
        #pragma unroll
        for (int ks = 0; ks < 4; ks++) {
            uint32_t bh[4], bl[4];
            uint32_t off = ((st * 64 + brow) * 72 + ks * 16 + bcol) * 2;
            ldsm4(bh, kHa + off);
            ldsm4(bl, kLa + off);
            #pragma unroll
            for (int mi = 0; mi < 2; mi++)
                #pragma unroll
                for (int nj = 0; nj < 2; nj++) {
                    mma_bf16(acc[mi][nj], ah[mi][ks], &bh[nj * 2]);
                    mma_bf16(acc[mi][nj], ah[mi][ks], &bl[nj * 2]);
                    mma_bf16(acc[mi][nj], al[mi][ks], &bh[nj * 2]);
                }
        }
        #pragma unroll
        for (int mi = 0; mi < 2; mi++)
            #pragma unroll
            for (int nj = 0; nj < 2; nj++) {
                int rloc = wm * 32 + mi * 16 + g;
                int sbase = st * 64 + wn * 16 + nj * 8 + l2 * 2;
                #pragma unroll
                for (int hf = 0; hf < 2; hf++) {
                    int row = rloc + hf * 8;
                    int t = t0 + row;
                    const float* prow = g_p + ((long)(b * Tn + t)) * 256;
                    float v0 = -1e30f, v1 = -1e30f;
                    if (sbase <= t)     v0 = acc[mi][nj][hf * 2]     + prow[sbase - t + 255];
                    if (sbase + 1 <= t) v1 = acc[mi][nj][hf * 2 + 1] + prow[sbase + 1 - t + 255];
                    float2 o = {v0, v1};
                    *(float2*)&sc[row * 264 + sbase] = o;
                }
            }
    }
    __syncthreads();   // scores complete; kh/kl free

    // ---- load live v rows into kh/kl (reused) ----
    for (int f = tid; f < send * 16; f += 256) {
        int r = f >> 4, c4 = (f & 15) << 2;
        float4 v = *(const float4*)(g_v + ((long)(b * Tn + r)) * Hn + c4);
        __nv_bfloat16 h0, l0, h1, l1, h2, l2b, h3, l3;
        split_bf(v.x, h0, l0); split_bf(v.y, h1, l1);
        split_bf(v.z, h2, l2b); split_bf(v.w, h3, l3);
        *(uint2*)(kh + r * 72 + c4) = {pk(h0, h1), pk(h2, h3)};
        *(uint2*)(kl + r * 72 + c4) = {pk(l0, l1), pk(l2b, l3)};
    }

    // ---- softmax (8 rows per warp, col pairs per lane) + bf16 hi/lo emit ----
    for (int r = w * 8; r < w * 8 + 8; r++) {
        float m = -1e30f;
        for (int i = 0; i < nst; i++) {
            float2 v = *(const float2*)&sc[r * 264 + i * 64 + lane * 2];
            m = fmaxf(m, fmaxf(v.x, v.y));
        }
        #pragma unroll
        for (int o = 16; o; o >>= 1) m = fmaxf(m, __shfl_xor_sync(0xffffffffu, m, o));
        float sum = 0.f;
        for (int i = 0; i < nst; i++) {
            float2 v = *(const float2*)&sc[r * 264 + i * 64 + lane * 2];
            v.x = __expf(v.x - m);
            v.y = __expf(v.y - m);
            sum += v.x + v.y;
            *(float2*)&sc[r * 264 + i * 64 + lane * 2] = v;
        }
        #pragma unroll
        for (int o = 16; o; o >>= 1) sum += __shfl_xor_sync(0xffffffffu, sum, o);
        float inv = 1.0f / sum;
        for (int i = 0; i < nst; i++) {
            float2 e = *(const float2*)&sc[r * 264 + i * 64 + lane * 2];
            float w0 = e.x * inv, w1 = e.y * inv;
            __nv_bfloat16 h0, l0, h1, l1;
            split_bf(w0, h0, l0);
            split_bf(w1, h1, l1);
            *(uint32_t*)&wh[r * 264 + i * 64 + lane * 2] = pk(h0, h1);
            *(uint32_t*)&wl[r * 264 + i * 64 + lane * 2] = pk(l0, l1);
        }
    }
    __syncthreads();   // weights + v ready

    // ---- out = wei @ v ----
    const int vrow = (lane & 7) + ((lane >> 3) & 1) * 8;
    const int vcol = wn * 16 + (lane >> 4) * 8;
    float oacc[2][2][4] = {};
    for (int st = 0; st < nst; st++) {
        #pragma unroll
        for (int ks = 0; ks < 4; ks++) {
            uint32_t aw[2][4], awl[2][4], bvh[4], bvl[4];
            uint32_t aoff = (arow * 264 + st * 64 + ks * 16 + acol) * 2;
            ldsm4(aw[0],  wHa + aoff);
            ldsm4(aw[1],  wHa + aoff + 16 * 264 * 2);
            ldsm4(awl[0], wLa + aoff);
            ldsm4(awl[1], wLa + aoff + 16 * 264 * 2);
            uint32_t voff = ((st * 64 + ks * 16 + vrow) * 72 + vcol) * 2;
            ldsm4t(bvh, kHa + voff);
            ldsm4t(bvl, kLa + voff);
            #pragma unroll
            for (int mi = 0; mi < 2; mi++)
                #pragma unroll
                for (int nj = 0; nj < 2; nj++) {
                    mma_bf16(oacc[mi][nj], aw[mi],  &bvh[nj * 2]);
                    mma_bf16(oacc[mi][nj], aw[mi],  &bvl[nj * 2]);
                    mma_bf16(oacc[mi][nj], awl[mi], &bvh[nj * 2]);
                }
        }
    }

    #pragma unroll
    for (int mi = 0; mi < 2; mi++) {
        int rr = t0 + wm * 32 + mi * 16 + g;
        #pragma unroll
        for (int nj = 0; nj < 2; nj++) {
            int col = wn * 16 + nj * 8 + l2 * 2;
            float2 o0 = {oacc[mi][nj][0], oacc[mi][nj][1]};
            float2 o1 = {oacc[mi][nj][2], oacc[mi][nj][3]};
            *(float2*)(out + ((long)(b * Tn + rr)) * Hn + col) = o0;
            *(float2*)(out + ((long)(b * Tn + rr + 8)) * Hn + col) = o1;
        }
    }
}

// ---------------------------------------------------------------------------
extern "C" void kernel_launch(void* const* d_in, const int* in_sizes, int n_in,
                              void* d_out, int out_size)
{
    const float* x  = (const float*)d_in[0];
    const float* Wk = (const float*)d_in[1];
    const float* Wq = (const float*)d_in[2];
    const float* Wv = (const float*)d_in[3];
    const float* E  = (const float*)d_in[4];
    float* out = (float*)d_out;

    setup_kernel<<<288, 256>>>(Wk, Wq, Wv, E);

    const int qkv_sm = (2 * 128 * 72 + 2 * 192 * 72) * (int)sizeof(__nv_bfloat16); // 92160
    cudaFuncSetAttribute(qkv_kernel, cudaFuncAttributeMaxDynamicSharedMemorySize, qkv_sm);
    qkv_kernel<<<Bn * Tn / 128, 512, qkv_sm>>>(x);

    const int pos_sm = (2 * 64 * 72 + 2 * 128 * 72) * (int)sizeof(__nv_bfloat16);  // 55296
    cudaFuncSetAttribute(pos_kernel, cudaFuncAttributeMaxDynamicSharedMemorySize, pos_sm);
    pos_kernel<<<dim3(Bn * Tn / 64, 2), 256, pos_sm>>>();

    const int attn_sm = 64 * 264 * 4 + 2 * 64 * 264 * 2 + 2 * 64 * 72 * 2
                      + 2 * 256 * 72 * 2;                                          // 227328
    cudaFuncSetAttribute(attn_kernel, cudaFuncAttributeMaxDynamicSharedMemorySize, attn_sm);
    attn_kernel<<<dim3(Bn, Tn / 64), 256, attn_sm>>>(out);
}

// round 7
// speedup vs baseline: 1.8060x; 1.0167x over previous
#include <cuda_runtime.h>
#include <cuda_bf16.h>
#include <cstdint>

#define Bn 256
#define Tn 256
#define Cn 256
#define Hn 64

// ---------------- scratch ----------------
__device__ float g_q[Bn*Tn*Hn];
__device__ float g_k[Bn*Tn*Hn];    // k * (1/8), scale folded into W image
__device__ float g_v[Bn*Tn*Hn];
__device__ float g_p[Bn*Tn*256];   // P[b,t,d] = q[b,t].E[d]
// pre-split, pad-72 bf16 operand images ([n][72] per K-chunk; pads zeroed)
__device__ __align__(16) __nv_bfloat16 g_Wh[4*192*72];  // [kt][n=192][72]
__device__ __align__(16) __nv_bfloat16 g_Wl[4*192*72];
__device__ __align__(16) __nv_bfloat16 g_Eh[256*72];    // [d][72]
__device__ __align__(16) __nv_bfloat16 g_El[256*72];

// ---------------- helpers ----------------
__device__ __forceinline__ uint32_t smem_u32(const void* p) {
    uint32_t a;
    asm("{ .reg .u64 t; cvta.to.shared.u64 t, %1; cvt.u32.u64 %0, t; }" : "=r"(a) : "l"(p));
    return a;
}
__device__ __forceinline__ void mma_bf16(float* c, const uint32_t* a, const uint32_t* b) {
    asm volatile(
        "mma.sync.aligned.m16n8k16.row.col.f32.bf16.bf16.f32 "
        "{%0,%1,%2,%3}, {%4,%5,%6,%7}, {%8,%9}, {%0,%1,%2,%3};"
        : "+f"(c[0]), "+f"(c[1]), "+f"(c[2]), "+f"(c[3])
        : "r"(a[0]), "r"(a[1]), "r"(a[2]), "r"(a[3]), "r"(b[0]), "r"(b[1]));
}
__device__ __forceinline__ void ldsm4(uint32_t* r, uint32_t addr) {
    asm volatile("ldmatrix.sync.aligned.m8n8.x4.shared.b16 {%0,%1,%2,%3}, [%4];"
        : "=r"(r[0]), "=r"(r[1]), "=r"(r[2]), "=r"(r[3]) : "r"(addr));
}
__device__ __forceinline__ void ldsm4t(uint32_t* r, uint32_t addr) {
    asm volatile("ldmatrix.sync.aligned.m8n8.x4.trans.shared.b16 {%0,%1,%2,%3}, [%4];"
        : "=r"(r[0]), "=r"(r[1]), "=r"(r[2]), "=r"(r[3]) : "r"(addr));
}
__device__ __forceinline__ void split_bf(float v, __nv_bfloat16& h, __nv_bfloat16& l) {
    h = __float2bfloat16(v);
    l = __float2bfloat16(v - __bfloat162float(h));
}
__device__ __forceinline__ uint32_t pk(__nv_bfloat16 a, __nv_bfloat16 b) {
    return (uint32_t)__bfloat16_as_ushort(a) | ((uint32_t)__bfloat16_as_ushort(b) << 16);
}

// ---------------------------------------------------------------------------
// Setup: build hi/lo pad-72 images of [Wq|Wk*0.125|Wv] and E.
// ---------------------------------------------------------------------------
__global__ __launch_bounds__(256) void setup_kernel(
    const float* __restrict__ Wk, const float* __restrict__ Wq,
    const float* __restrict__ Wv, const float* __restrict__ E)
{
    int id = blockIdx.x * 256 + threadIdx.x;
    if (id < 4 * 192 * 72) {
        int kt = id / (192 * 72);
        int rem = id % (192 * 72);
        int n = rem / 72, k = rem % 72;
        float v = 0.f;
        if (k < 64) {
            int which = n >> 6, col = n & 63;
            const float* W = (which == 0) ? Wq : (which == 1) ? Wk : Wv;
            v = W[(kt * 64 + k) * Hn + col];
            if (which == 1) v *= 0.125f;
        }
        __nv_bfloat16 h, l;
        split_bf(v, h, l);
        g_Wh[id] = h;
        g_Wl[id] = l;
    } else {
        int id2 = id - 4 * 192 * 72;
        if (id2 < 256 * 72) {
            int d = id2 / 72, k = id2 % 72;
            float v = (k < 64) ? E[d * Hn + k] : 0.f;
            __nv_bfloat16 h, l;
            split_bf(v, h, l);
            g_Eh[id2] = h;
            g_El[id2] = l;
        }
    }
}

// ---------------------------------------------------------------------------
// Fused qkv GEMM (bf16x3, ldmatrix). grid=512, block=512. (unchanged, R5)
// ---------------------------------------------------------------------------
__global__ __launch_bounds__(512) void qkv_kernel(const float* __restrict__ x)
{
    extern __shared__ __nv_bfloat16 smb[];
    __nv_bfloat16* Ah = smb;
    __nv_bfloat16* Al = Ah + 128 * 72;
    __nv_bfloat16* Bh = Al + 128 * 72;
    __nv_bfloat16* Bl = Bh + 192 * 72;

    const int row0 = blockIdx.x * 128;
    const int tid = threadIdx.x, w = tid >> 5, lane = tid & 31;
    const int wm = w >> 2, wn = w & 3;
    const int g = lane >> 2, l2 = lane & 3;

    const uint32_t aH = smem_u32(Ah), aL = smem_u32(Al);
    const uint32_t bH = smem_u32(Bh), bL = smem_u32(Bl);
    const int arow = wm * 32 + (lane & 15);
    const int acol = (lane >> 4) * 8;
    const int brow = wn * 48 + (lane & 7) + (lane >> 4) * 8;
    const int bcol = ((lane >> 3) & 1) * 8;

    float acc[2][6][4] = {};

    for (int ct = 0; ct < 4; ct++) {
        float4 xv[4];
        #pragma unroll
        for (int i = 0; i < 4; i++) {
            int f = tid + i * 512;
            int r = f >> 4, c4 = (f & 15) << 2;
            xv[i] = *(const float4*)(x + (row0 + r) * Cn + ct * 64 + c4);
        }
        __syncthreads();

        #pragma unroll
        for (int i = 0; i < 4; i++) {
            int f = tid + i * 512;
            int r = f >> 4, c4 = (f & 15) << 2;
            __nv_bfloat16 h0, l0, h1, l1, h2, l2b, h3, l3;
            split_bf(xv[i].x, h0, l0);
            split_bf(xv[i].y, h1, l1);
            split_bf(xv[i].z, h2, l2b);
            split_bf(xv[i].w, h3, l3);
            uint2 uh = {pk(h0, h1), pk(h2, h3)};
            uint2 ul = {pk(l0, l1), pk(l2b, l3)};
            *(uint2*)(Ah + r * 72 + c4) = uh;
            *(uint2*)(Al + r * 72 + c4) = ul;
        }
        {
            uint4* dh = (uint4*)Bh;
            uint4* dl = (uint4*)Bl;
            const uint4* sh = (const uint4*)(g_Wh + ct * 192 * 72);
            const uint4* sl = (const uint4*)(g_Wl + ct * 192 * 72);
            #pragma unroll
            for (int idx = tid; idx < 1728; idx += 512) {
                dh[idx] = sh[idx];
                dl[idx] = sl[idx];
            }
        }
        __syncthreads();

        #pragma unroll
        for (int ks = 0; ks < 64; ks += 16) {
            uint32_t ah[2][4], al[2][4], bh[3][4], bl[3][4];
            #pragma unroll
            for (int mi = 0; mi < 2; mi++) {
                uint32_t off = ((arow + mi * 16) * 72 + ks + acol) * 2;
                ldsm4(ah[mi], aH + off);
                ldsm4(al[mi], aL + off);
            }
            #pragma unroll
            for (int nj = 0; nj < 3; nj++) {
                uint32_t off = ((brow + nj * 16) * 72 + ks + bcol) * 2;
                ldsm4(bh[nj], bH + off);
                ldsm4(bl[nj], bL + off);
            }
            #pragma unroll
            for (int mi = 0; mi < 2; mi++)
                #pragma unroll
                for (int ni = 0; ni < 6; ni++) {
                    const uint32_t* ph = &bh[ni >> 1][(ni & 1) * 2];
                    const uint32_t* pl = &bl[ni >> 1][(ni & 1) * 2];
                    mma_bf16(acc[mi][ni], ah[mi], ph);
                    mma_bf16(acc[mi][ni], ah[mi], pl);
                    mma_bf16(acc[mi][ni], al[mi], ph);
                }
        }
    }

    #pragma unroll
    for (int mi = 0; mi < 2; mi++) {
        int rr = row0 + wm * 32 + mi * 16 + g;
        #pragma unroll
        for (int ni = 0; ni < 6; ni++) {
            int n = wn * 48 + ni * 8 + l2 * 2;
            float* outp = (n < 64) ? g_q : (n < 128) ? g_k : g_v;
            int col = n & 63;
            float2 o0 = {acc[mi][ni][0], acc[mi][ni][1]};
            float2 o1 = {acc[mi][ni][2], acc[mi][ni][3]};
            *(float2*)(outp + rr * Hn + col) = o0;
            *(float2*)(outp + (rr + 8) * Hn + col) = o1;
        }
    }
}

// ---------------------------------------------------------------------------
// pos: P = q @ E^T (bf16x3, ldmatrix). grid=(1024,2), block=256. (unchanged)
// ---------------------------------------------------------------------------
__global__ __launch_bounds__(256) void pos_kernel()
{
    const int row0  = blockIdx.x * 64;
    const int t0    = row0 & 255;
    const int nbase = blockIdx.y * 128;
    const int dmin  = 192 - t0;
    if (nbase + 127 < dmin) return;

    extern __shared__ __nv_bfloat16 smb[];
    __nv_bfloat16* Ah = smb;
    __nv_bfloat16* Al = Ah + 64 * 72;
    __nv_bfloat16* Eh = Al + 64 * 72;
    __nv_bfloat16* El = Eh + 128 * 72;

    const int tid = threadIdx.x, w = tid >> 5, lane = tid & 31;
    const int wm = w >> 2, wn = w & 3;
    const int g = lane >> 2, l2 = lane & 3;

    #pragma unroll
    for (int i = 0; i < 4; i++) {
        int f = tid + i * 256;
        int r = f >> 4, c4 = (f & 15) << 2;
        float4 v = *(const float4*)(g_q + (row0 + r) * Hn + c4);
        __nv_bfloat16 h0, l0, h1, l1, h2, l2b, h3, l3;
        split_bf(v.x, h0, l0);
        split_bf(v.y, h1, l1);
        split_bf(v.z, h2, l2b);
        split_bf(v.w, h3, l3);
        uint2 uh = {pk(h0, h1), pk(h2, h3)};
        uint2 ul = {pk(l0, l1), pk(l2b, l3)};
        *(uint2*)(Ah + r * 72 + c4) = uh;
        *(uint2*)(Al + r * 72 + c4) = ul;
    }
    {
        uint4* dh = (uint4*)Eh;
        uint4* dl = (uint4*)El;
        const uint4* sh = (const uint4*)(g_Eh + nbase * 72);
        const uint4* sl = (const uint4*)(g_El + nbase * 72);
        #pragma unroll
        for (int idx = tid; idx < 1152; idx += 256) {
            dh[idx] = sh[idx];
            dl[idx] = sl[idx];
        }
    }
    __syncthreads();

    if (nbase + wn * 32 + 31 < dmin) return;

    const uint32_t aH = smem_u32(Ah), aL = smem_u32(Al);
    const uint32_t bH = smem_u32(Eh), bL = smem_u32(El);
    const int arow = wm * 32 + (lane & 15);
    const int acol = (lane >> 4) * 8;
    const int brow = wn * 32 + (lane & 7) + (lane >> 4) * 8;
    const int bcol = ((lane >> 3) & 1) * 8;

    float acc[2][4][4] = {};
    #pragma unroll
    for (int ks = 0; ks < 64; ks += 16) {
        uint32_t ah[2][4], al[2][4], bh[2][4], bl[2][4];
        #pragma unroll
        for (int mi = 0; mi < 2; mi++) {
            uint32_t off = ((arow + mi * 16) * 72 + ks + acol) * 2;
            ldsm4(ah[mi], aH + off);
            ldsm4(al[mi], aL + off);
        }
        #pragma unroll
        for (int nj = 0; nj < 2; nj++) {
            uint32_t off = ((brow + nj * 16) * 72 + ks + bcol) * 2;
            ldsm4(bh[nj], bH + off);
            ldsm4(bl[nj], bL + off);
        }
        #pragma unroll
        for (int mi = 0; mi < 2; mi++)
            #pragma unroll
            for (int ni = 0; ni < 4; ni++) {
                const uint32_t* ph = &bh[ni >> 1][(ni & 1) * 2];
                const uint32_t* pl = &bl[ni >> 1][(ni & 1) * 2];
                mma_bf16(acc[mi][ni], ah[mi], ph);
                mma_bf16(acc[mi][ni], ah[mi], pl);
                mma_bf16(acc[mi][ni], al[mi], ph);
            }
    }

    #pragma unroll
    for (int mi = 0; mi < 2; mi++) {
        int rr = row0 + wm * 32 + mi * 16 + g;
        int t1 = rr & 255, t2 = (rr + 8) & 255;
        #pragma unroll
        for (int ni = 0; ni < 4; ni++) {
            int c = nbase + wn * 32 + ni * 8 + l2 * 2;
            if (c + 1 >= 255 - t1) {
                float2 o = {acc[mi][ni][0], acc[mi][ni][1]};
                *(float2*)(g_p + (long)rr * 256 + c) = o;
            }
            if (c + 1 >= 255 - t2) {
                float2 o = {acc[mi][ni][2], acc[mi][ni][3]};
                *(float2*)(g_p + (long)(rr + 8) * 256 + c) = o;
            }
        }
    }
}

// ---------------------------------------------------------------------------
// attention via bf16x3 mma. grid=(256,4), block=512 (16 warps).
// Score: warps 2m x 8n, one 32x32 tile each (no loop). PV: split-K,
// warps (2m x 2n x 4k), fp32 slice reduction through sc. 227,328 B smem.
// ---------------------------------------------------------------------------
__global__ __launch_bounds__(512) void attn_kernel(float* __restrict__ out)
{
    extern __shared__ char smc[];
    float* sc = (float*)smc;                                   // 64*264 f32
    __nv_bfloat16* wh = (__nv_bfloat16*)(smc + 64 * 264 * 4);  // 64*264
    __nv_bfloat16* wl = wh + 64 * 264;
    __nv_bfloat16* qh = wl + 64 * 264;                         // 64*72
    __nv_bfloat16* ql = qh + 64 * 72;
    __nv_bfloat16* kh = ql + 64 * 72;                          // 256*72
    __nv_bfloat16* kl = kh + 256 * 72;

    const int b  = blockIdx.x;
    const int tt = blockIdx.y;
    const int t0 = tt * 64;
    const int nst = tt + 1;
    const int send = nst * 64;
    const int tid = threadIdx.x, w = tid >> 5, lane = tid & 31;
    const int g = lane >> 2, l2 = lane & 3;

    const uint32_t qHa = smem_u32(qh), qLa = smem_u32(ql);
    const uint32_t kHa = smem_u32(kh), kLa = smem_u32(kl);
    const uint32_t wHa = smem_u32(wh), wLa = smem_u32(wl);

    // ---- load q tile (64x64) and live k rows, split hi/lo ----
    #pragma unroll
    for (int i = 0; i < 2; i++) {
        int f = tid + i * 512;
        int r = f >> 4, c4 = (f & 15) << 2;
        float4 v = *(const float4*)(g_q + ((long)(b * Tn + t0 + r)) * Hn + c4);
        __nv_bfloat16 h0, l0, h1, l1, h2, l2b, h3, l3;
        split_bf(v.x, h0, l0); split_bf(v.y, h1, l1);
        split_bf(v.z, h2, l2b); split_bf(v.w, h3, l3);
        *(uint2*)(qh + r * 72 + c4) = {pk(h0, h1), pk(h2, h3)};
        *(uint2*)(ql + r * 72 + c4) = {pk(l0, l1), pk(l2b, l3)};
    }
    for (int f = tid; f < send * 16; f += 512) {
        int r = f >> 4, c4 = (f & 15) << 2;
        float4 v = *(const float4*)(g_k + ((long)(b * Tn + r)) * Hn + c4);
        __nv_bfloat16 h0, l0, h1, l1, h2, l2b, h3, l3;
        split_bf(v.x, h0, l0); split_bf(v.y, h1, l1);
        split_bf(v.z, h2, l2b); split_bf(v.w, h3, l3);
        *(uint2*)(kh + r * 72 + c4) = {pk(h0, h1), pk(h2, h3)};
        *(uint2*)(kl + r * 72 + c4) = {pk(l0, l1), pk(l2b, l3)};
    }
    __syncthreads();

    // ---- score phase: warps 2m x 8n, one 32x32 tile each ----
    {
        const int wm = w >> 3, wn = w & 7;
        const int cb = wn * 32;                 // key-col base
        if (cb < send) {
            const int arow = wm * 32 + (lane & 15);
            const int acol = (lane >> 4) * 8;
            const int brow = cb + (lane & 7) + (lane >> 4) * 8;
            const int bcol = ((lane >> 3) & 1) * 8;
            float acc[2][4][4] = {};
            #pragma unroll
            for (int ks = 0; ks < 4; ks++) {
                uint32_t ah[2][4], al[2][4], bh[2][4], bl[2][4];
                #pragma unroll
                for (int mi = 0; mi < 2; mi++) {
                    uint32_t off = ((arow + mi * 16) * 72 + ks * 16 + acol) * 2;
                    ldsm4(ah[mi], qHa + off);
                    ldsm4(al[mi], qLa + off);
                }
                #pragma unroll
                for (int nj = 0; nj < 2; nj++) {
                    uint32_t off = ((brow + nj * 16) * 72 + ks * 16 + bcol) * 2;
                    ldsm4(bh[nj], kHa + off);
                    ldsm4(bl[nj], kLa + off);
                }
                #pragma unroll
                for (int mi = 0; mi < 2; mi++)
                    #pragma unroll
                    for (int ni = 0; ni < 4; ni++) {
                        const uint32_t* ph = &bh[ni >> 1][(ni & 1) * 2];
                        const uint32_t* pl = &bl[ni >> 1][(ni & 1) * 2];
                        mma_bf16(acc[mi][ni], ah[mi], ph);
                        mma_bf16(acc[mi][ni], ah[mi], pl);
                        mma_bf16(acc[mi][ni], al[mi], ph);
                    }
            }
            #pragma unroll
            for (int mi = 0; mi < 2; mi++)
                #pragma unroll
                for (int ni = 0; ni < 4; ni++) {
                    int rloc = wm * 32 + mi * 16 + g;
                    int sbase = cb + ni * 8 + l2 * 2;
                    #pragma unroll
                    for (int hf = 0; hf < 2; hf++) {
                        int row = rloc + hf * 8;
                        int t = t0 + row;
                        const float* prow = g_p + ((long)(b * Tn + t)) * 256;
                        float v0 = -1e30f, v1 = -1e30f;
                        if (sbase <= t)     v0 = acc[mi][ni][hf * 2]     + prow[sbase - t + 255];
                        if (sbase + 1 <= t) v1 = acc[mi][ni][hf * 2 + 1] + prow[sbase + 1 - t + 255];
                        float2 o = {v0, v1};
                        *(float2*)&sc[row * 264 + sbase] = o;
                    }
                }
        }
    }
    __syncthreads();   // scores complete; kh/kl free

    // ---- load live v rows into kh/kl (overlaps softmax) ----
    for (int f = tid; f < send * 16; f += 512) {
        int r = f >> 4, c4 = (f & 15) << 2;
        float4 v = *(const float4*)(g_v + ((long)(b * Tn + r)) * Hn + c4);
        __nv_bfloat16 h0, l0, h1, l1, h2, l2b, h3, l3;
        split_bf(v.x, h0, l0); split_bf(v.y, h1, l1);
        split_bf(v.z, h2, l2b); split_bf(v.w, h3, l3);
        *(uint2*)(kh + r * 72 + c4) = {pk(h0, h1), pk(h2, h3)};
        *(uint2*)(kl + r * 72 + c4) = {pk(l0, l1), pk(l2b, l3)};
    }

    // ---- softmax: 16 warps x 4 rows, bf16 hi/lo weight emit ----
    for (int r = w * 4; r < w * 4 + 4; r++) {
        float m = -1e30f;
        for (int i = 0; i < nst; i++) {
            float2 v = *(const float2*)&sc[r * 264 + i * 64 + lane * 2];
            m = fmaxf(m, fmaxf(v.x, v.y));
        }
        #pragma unroll
        for (int o = 16; o; o >>= 1) m = fmaxf(m, __shfl_xor_sync(0xffffffffu, m, o));
        float sum = 0.f;
        for (int i = 0; i < nst; i++) {
            float2 v = *(const float2*)&sc[r * 264 + i * 64 + lane * 2];
            v.x = __expf(v.x - m);
            v.y = __expf(v.y - m);
            sum += v.x + v.y;
            *(float2*)&sc[r * 264 + i * 64 + lane * 2] = v;
        }
        #pragma unroll
        for (int o = 16; o; o >>= 1) sum += __shfl_xor_sync(0xffffffffu, sum, o);
        float inv = 1.0f / sum;
        for (int i = 0; i < nst; i++) {
            float2 e = *(const float2*)&sc[r * 264 + i * 64 + lane * 2];
            float w0 = e.x * inv, w1 = e.y * inv;
            __nv_bfloat16 h0, l0, h1, l1;
            split_bf(w0, h0, l0);
            split_bf(w1, h1, l1);
            *(uint32_t*)&wh[r * 264 + i * 64 + lane * 2] = pk(h0, h1);
            *(uint32_t*)&wl[r * 264 + i * 64 + lane * 2] = pk(l0, l1);
        }
    }
    __syncthreads();   // weights + v ready; sc free

    // ---- out = wei @ v : split-K over warps (2m x 2n x 4k) ----
    {
        const int wk = w & 3;
        const int wn2 = (w >> 2) & 1;
        const int wm2 = w >> 3;
        if (wk < nst) {
            const int arow = wm2 * 32 + (lane & 15);
            const int acol = (lane >> 4) * 8;
            const int vrow = (lane & 7) + ((lane >> 3) & 1) * 8;
            const int vcol = wn2 * 32 + (lane >> 4) * 8;
            float oacc[2][4][4] = {};
            #pragma unroll
            for (int ks = 0; ks < 4; ks++) {
                uint32_t aw[2][4], awl[2][4], bvh[2][4], bvl[2][4];
                #pragma unroll
                for (int mi = 0; mi < 2; mi++) {
                    uint32_t aoff = ((arow + mi * 16) * 264 + wk * 64 + ks * 16 + acol) * 2;
                    ldsm4(aw[mi],  wHa + aoff);
                    ldsm4(awl[mi], wLa + aoff);
                }
                #pragma unroll
                for (int nj = 0; nj < 2; nj++) {
                    uint32_t voff = ((wk * 64 + ks * 16 + vrow) * 72 + vcol + nj * 16) * 2;
                    ldsm4t(bvh[nj], kHa + voff);
                    ldsm4t(bvl[nj], kLa + voff);
                }
                #pragma unroll
                for (int mi = 0; mi < 2; mi++)
                    #pragma unroll
                    for (int ni = 0; ni < 4; ni++) {
                        const uint32_t* ph = &bvh[ni >> 1][(ni & 1) * 2];
                        const uint32_t* pl = &bvl[ni >> 1][(ni & 1) * 2];
                        mma_bf16(oacc[mi][ni], aw[mi],  ph);
                        mma_bf16(oacc[mi][ni], aw[mi],  pl);
                        mma_bf16(oacc[mi][ni], awl[mi], ph);
                    }
            }
            // write slice wk to sc
            float* slice = sc + wk * 4096;
            #pragma unroll
            for (int mi = 0; mi < 2; mi++)
                #pragma unroll
                for (int ni = 0; ni < 4; ni++) {
                    int row = wm2 * 32 + mi * 16 + g;
                    int col = wn2 * 32 + ni * 8 + l2 * 2;
                    float2 o0 = {oacc[mi][ni][0], oacc[mi][ni][1]};
                    float2 o1 = {oacc[mi][ni][2], oacc[mi][ni][3]};
                    *(float2*)&slice[row * 64 + col] = o0;
                    *(float2*)&slice[(row + 8) * 64 + col] = o1;
                }
        }
    }
    __syncthreads();

    // ---- reduce nst slices and store ----
    #pragma unroll
    for (int i = 0; i < 8; i++) {
        int idx = tid + i * 512;
        float s = sc[idx];
        for (int j = 1; j < nst; j++) s += sc[j * 4096 + idx];
        int row = idx >> 6, col = idx & 63;
        out[((long)(b * Tn + t0 + row)) * Hn + col] = s;
    }
}

// ---------------------------------------------------------------------------
extern "C" void kernel_launch(void* const* d_in, const int* in_sizes, int n_in,
                              void* d_out, int out_size)
{
    const float* x  = (const float*)d_in[0];
    const float* Wk = (const float*)d_in[1];
    const float* Wq = (const float*)d_in[2];
    const float* Wv = (const float*)d_in[3];
    const float* E  = (const float*)d_in[4];
    float* out = (float*)d_out;

    setup_kernel<<<288, 256>>>(Wk, Wq, Wv, E);

    const int qkv_sm = (2 * 128 * 72 + 2 * 192 * 72) * (int)sizeof(__nv_bfloat16); // 92160
    cudaFuncSetAttribute(qkv_kernel, cudaFuncAttributeMaxDynamicSharedMemorySize, qkv_sm);
    qkv_kernel<<<Bn * Tn / 128, 512, qkv_sm>>>(x);

    const int pos_sm = (2 * 64 * 72 + 2 * 128 * 72) * (int)sizeof(__nv_bfloat16);  // 55296
    cudaFuncSetAttribute(pos_kernel, cudaFuncAttributeMaxDynamicSharedMemorySize, pos_sm);
    pos_kernel<<<dim3(Bn * Tn / 64, 2), 256, pos_sm>>>();

    const int attn_sm = 64 * 264 * 4 + 2 * 64 * 264 * 2 + 2 * 64 * 72 * 2
                      + 2 * 256 * 72 * 2;                                          // 227328
    cudaFuncSetAttribute(attn_kernel, cudaFuncAttributeMaxDynamicSharedMemorySize, attn_sm);
    attn_kernel<<<dim3(Bn, Tn / 64), 512, attn_sm>>>(out);
}

// round 8
// speedup vs baseline: 1.8874x; 1.0451x over previous
#include <cuda_runtime.h>
#include <cuda_bf16.h>
#include <cstdint>

#define Bn 256
#define Tn 256
#define Cn 256
#define Hn 64

// ---------------- scratch ----------------
__device__ float g_q[Bn*Tn*Hn];
__device__ float g_k[Bn*Tn*Hn];    // k * (1/8), scale folded into W image
__device__ float g_v[Bn*Tn*Hn];
__device__ float g_p[Bn*Tn*256];   // P[b,t,d] = q[b,t].E[d]
// pre-split, pad-72 bf16 operand images ([n][72] per K-chunk; pads zeroed)
__device__ __align__(16) __nv_bfloat16 g_Wh[4*192*72];  // [kt][n=192][72]
__device__ __align__(16) __nv_bfloat16 g_Wl[4*192*72];
__device__ __align__(16) __nv_bfloat16 g_Eh[256*72];    // [d][72]
__device__ __align__(16) __nv_bfloat16 g_El[256*72];

// ---------------- helpers ----------------
__device__ __forceinline__ uint32_t smem_u32(const void* p) {
    uint32_t a;
    asm("{ .reg .u64 t; cvta.to.shared.u64 t, %1; cvt.u32.u64 %0, t; }" : "=r"(a) : "l"(p));
    return a;
}
__device__ __forceinline__ void mma_bf16(float* c, const uint32_t* a, const uint32_t* b) {
    asm volatile(
        "mma.sync.aligned.m16n8k16.row.col.f32.bf16.bf16.f32 "
        "{%0,%1,%2,%3}, {%4,%5,%6,%7}, {%8,%9}, {%0,%1,%2,%3};"
        : "+f"(c[0]), "+f"(c[1]), "+f"(c[2]), "+f"(c[3])
        : "r"(a[0]), "r"(a[1]), "r"(a[2]), "r"(a[3]), "r"(b[0]), "r"(b[1]));
}
__device__ __forceinline__ void ldsm4(uint32_t* r, uint32_t addr) {
    asm volatile("ldmatrix.sync.aligned.m8n8.x4.shared.b16 {%0,%1,%2,%3}, [%4];"
        : "=r"(r[0]), "=r"(r[1]), "=r"(r[2]), "=r"(r[3]) : "r"(addr));
}
__device__ __forceinline__ void ldsm4t(uint32_t* r, uint32_t addr) {
    asm volatile("ldmatrix.sync.aligned.m8n8.x4.trans.shared.b16 {%0,%1,%2,%3}, [%4];"
        : "=r"(r[0]), "=r"(r[1]), "=r"(r[2]), "=r"(r[3]) : "r"(addr));
}
__device__ __forceinline__ void split_bf(float v, __nv_bfloat16& h, __nv_bfloat16& l) {
    h = __float2bfloat16(v);
    l = __float2bfloat16(v - __bfloat162float(h));
}
__device__ __forceinline__ uint32_t pk(__nv_bfloat16 a, __nv_bfloat16 b) {
    return (uint32_t)__bfloat16_as_ushort(a) | ((uint32_t)__bfloat16_as_ushort(b) << 16);
}

// ---------------------------------------------------------------------------
// Setup: build hi/lo pad-72 images of [Wq|Wk*0.125|Wv] and E.
// ---------------------------------------------------------------------------
__global__ __launch_bounds__(256) void setup_kernel(
    const float* __restrict__ Wk, const float* __restrict__ Wq,
    const float* __restrict__ Wv, const float* __restrict__ E)
{
    int id = blockIdx.x * 256 + threadIdx.x;
    if (id < 4 * 192 * 72) {
        int kt = id / (192 * 72);
        int rem = id % (192 * 72);
        int n = rem / 72, k = rem % 72;
        float v = 0.f;
        if (k < 64) {
            int which = n >> 6, col = n & 63;
            const float* W = (which == 0) ? Wq : (which == 1) ? Wk : Wv;
            v = W[(kt * 64 + k) * Hn + col];
            if (which == 1) v *= 0.125f;
        }
        __nv_bfloat16 h, l;
        split_bf(v, h, l);
        g_Wh[id] = h;
        g_Wl[id] = l;
    } else {
        int id2 = id - 4 * 192 * 72;
        if (id2 < 256 * 72) {
            int d = id2 / 72, k = id2 % 72;
            float v = (k < 64) ? E[d * Hn + k] : 0.f;
            __nv_bfloat16 h, l;
            split_bf(v, h, l);
            g_Eh[id2] = h;
            g_El[id2] = l;
        }
    }
}

// ---------------------------------------------------------------------------
// Fused qkv GEMM (bf16x3, ldmatrix). grid=512, block=512.
// __launch_bounds__(512,1): full 128-reg budget, no spills (1 CTA/SM anyway).
// ---------------------------------------------------------------------------
__global__ __launch_bounds__(512, 1) void qkv_kernel(const float* __restrict__ x)
{
    extern __shared__ __nv_bfloat16 smb[];
    __nv_bfloat16* Ah = smb;
    __nv_bfloat16* Al = Ah + 128 * 72;
    __nv_bfloat16* Bh = Al + 128 * 72;
    __nv_bfloat16* Bl = Bh + 192 * 72;

    const int row0 = blockIdx.x * 128;
    const int tid = threadIdx.x, w = tid >> 5, lane = tid & 31;
    const int wm = w >> 2, wn = w & 3;
    const int g = lane >> 2, l2 = lane & 3;

    const uint32_t aH = smem_u32(Ah), aL = smem_u32(Al);
    const uint32_t bH = smem_u32(Bh), bL = smem_u32(Bl);
    const int arow = wm * 32 + (lane & 15);
    const int acol = (lane >> 4) * 8;
    const int brow = wn * 48 + (lane & 7) + (lane >> 4) * 8;
    const int bcol = ((lane >> 3) & 1) * 8;

    float acc[2][6][4] = {};

    for (int ct = 0; ct < 4; ct++) {
        float4 xv[4];
        #pragma unroll
        for (int i = 0; i < 4; i++) {
            int f = tid + i * 512;
            int r = f >> 4, c4 = (f & 15) << 2;
            xv[i] = *(const float4*)(x + (row0 + r) * Cn + ct * 64 + c4);
        }
        __syncthreads();

        #pragma unroll
        for (int i = 0; i < 4; i++) {
            int f = tid + i * 512;
            int r = f >> 4, c4 = (f & 15) << 2;
            __nv_bfloat16 h0, l0, h1, l1, h2, l2b, h3, l3;
            split_bf(xv[i].x, h0, l0);
            split_bf(xv[i].y, h1, l1);
            split_bf(xv[i].z, h2, l2b);
            split_bf(xv[i].w, h3, l3);
            uint2 uh = {pk(h0, h1), pk(h2, h3)};
            uint2 ul = {pk(l0, l1), pk(l2b, l3)};
            *(uint2*)(Ah + r * 72 + c4) = uh;
            *(uint2*)(Al + r * 72 + c4) = ul;
        }
        {
            uint4* dh = (uint4*)Bh;
            uint4* dl = (uint4*)Bl;
            const uint4* sh = (const uint4*)(g_Wh + ct * 192 * 72);
            const uint4* sl = (const uint4*)(g_Wl + ct * 192 * 72);
            #pragma unroll
            for (int idx = tid; idx < 1728; idx += 512) {
                dh[idx] = sh[idx];
                dl[idx] = sl[idx];
            }
        }
        __syncthreads();

        #pragma unroll
        for (int ks = 0; ks < 64; ks += 16) {
            uint32_t ah[2][4], al[2][4], bh[3][4], bl[3][4];
            #pragma unroll
            for (int mi = 0; mi < 2; mi++) {
                uint32_t off = ((arow + mi * 16) * 72 + ks + acol) * 2;
                ldsm4(ah[mi], aH + off);
                ldsm4(al[mi], aL + off);
            }
            #pragma unroll
            for (int nj = 0; nj < 3; nj++) {
                uint32_t off = ((brow + nj * 16) * 72 + ks + bcol) * 2;
                ldsm4(bh[nj], bH + off);
                ldsm4(bl[nj], bL + off);
            }
            #pragma unroll
            for (int mi = 0; mi < 2; mi++)
                #pragma unroll
                for (int ni = 0; ni < 6; ni++) {
                    const uint32_t* ph = &bh[ni >> 1][(ni & 1) * 2];
                    const uint32_t* pl = &bl[ni >> 1][(ni & 1) * 2];
                    mma_bf16(acc[mi][ni], ah[mi], ph);
                    mma_bf16(acc[mi][ni], ah[mi], pl);
                    mma_bf16(acc[mi][ni], al[mi], ph);
                }
        }
    }

    #pragma unroll
    for (int mi = 0; mi < 2; mi++) {
        int rr = row0 + wm * 32 + mi * 16 + g;
        #pragma unroll
        for (int ni = 0; ni < 6; ni++) {
            int n = wn * 48 + ni * 8 + l2 * 2;
            float* outp = (n < 64) ? g_q : (n < 128) ? g_k : g_v;
            int col = n & 63;
            float2 o0 = {acc[mi][ni][0], acc[mi][ni][1]};
            float2 o1 = {acc[mi][ni][2], acc[mi][ni][3]};
            *(float2*)(outp + rr * Hn + col) = o0;
            *(float2*)(outp + (rr + 8) * Hn + col) = o1;
        }
    }
}

// ---------------------------------------------------------------------------
// pos: P = q @ E^T (bf16x3, ldmatrix). grid=(1024,2), block=256. (unchanged)
// ---------------------------------------------------------------------------
__global__ __launch_bounds__(256) void pos_kernel()
{
    const int row0  = blockIdx.x * 64;
    const int t0    = row0 & 255;
    const int nbase = blockIdx.y * 128;
    const int dmin  = 192 - t0;
    if (nbase + 127 < dmin) return;

    extern __shared__ __nv_bfloat16 smb[];
    __nv_bfloat16* Ah = smb;
    __nv_bfloat16* Al = Ah + 64 * 72;
    __nv_bfloat16* Eh = Al + 64 * 72;
    __nv_bfloat16* El = Eh + 128 * 72;

    const int tid = threadIdx.x, w = tid >> 5, lane = tid & 31;
    const int wm = w >> 2, wn = w & 3;
    const int g = lane >> 2, l2 = lane & 3;

    #pragma unroll
    for (int i = 0; i < 4; i++) {
        int f = tid + i * 256;
        int r = f >> 4, c4 = (f & 15) << 2;
        float4 v = *(const float4*)(g_q + (row0 + r) * Hn + c4);
        __nv_bfloat16 h0, l0, h1, l1, h2, l2b, h3, l3;
        split_bf(v.x, h0, l0);
        split_bf(v.y, h1, l1);
        split_bf(v.z, h2, l2b);
        split_bf(v.w, h3, l3);
        uint2 uh = {pk(h0, h1), pk(h2, h3)};
        uint2 ul = {pk(l0, l1), pk(l2b, l3)};
        *(uint2*)(Ah + r * 72 + c4) = uh;
        *(uint2*)(Al + r * 72 + c4) = ul;
    }
    {
        uint4* dh = (uint4*)Eh;
        uint4* dl = (uint4*)El;
        const uint4* sh = (const uint4*)(g_Eh + nbase * 72);
        const uint4* sl = (const uint4*)(g_El + nbase * 72);
        #pragma unroll
        for (int idx = tid; idx < 1152; idx += 256) {
            dh[idx] = sh[idx];
            dl[idx] = sl[idx];
        }
    }
    __syncthreads();

    if (nbase + wn * 32 + 31 < dmin) return;

    const uint32_t aH = smem_u32(Ah), aL = smem_u32(Al);
    const uint32_t bH = smem_u32(Eh), bL = smem_u32(El);
    const int arow = wm * 32 + (lane & 15);
    const int acol = (lane >> 4) * 8;
    const int brow = wn * 32 + (lane & 7) + (lane >> 4) * 8;
    const int bcol = ((lane >> 3) & 1) * 8;

    float acc[2][4][4] = {};
    #pragma unroll
    for (int ks = 0; ks < 64; ks += 16) {
        uint32_t ah[2][4], al[2][4], bh[2][4], bl[2][4];
        #pragma unroll
        for (int mi = 0; mi < 2; mi++) {
            uint32_t off = ((arow + mi * 16) * 72 + ks + acol) * 2;
            ldsm4(ah[mi], aH + off);
            ldsm4(al[mi], aL + off);
        }
        #pragma unroll
        for (int nj = 0; nj < 2; nj++) {
            uint32_t off = ((brow + nj * 16) * 72 + ks + bcol) * 2;
            ldsm4(bh[nj], bH + off);
            ldsm4(bl[nj], bL + off);
        }
        #pragma unroll
        for (int mi = 0; mi < 2; mi++)
            #pragma unroll
            for (int ni = 0; ni < 4; ni++) {
                const uint32_t* ph = &bh[ni >> 1][(ni & 1) * 2];
                const uint32_t* pl = &bl[ni >> 1][(ni & 1) * 2];
                mma_bf16(acc[mi][ni], ah[mi], ph);
                mma_bf16(acc[mi][ni], ah[mi], pl);
                mma_bf16(acc[mi][ni], al[mi], ph);
            }
    }

    #pragma unroll
    for (int mi = 0; mi < 2; mi++) {
        int rr = row0 + wm * 32 + mi * 16 + g;
        int t1 = rr & 255, t2 = (rr + 8) & 255;
        #pragma unroll
        for (int ni = 0; ni < 4; ni++) {
            int c = nbase + wn * 32 + ni * 8 + l2 * 2;
            if (c + 1 >= 255 - t1) {
                float2 o = {acc[mi][ni][0], acc[mi][ni][1]};
                *(float2*)(g_p + (long)rr * 256 + c) = o;
            }
            if (c + 1 >= 255 - t2) {
                float2 o = {acc[mi][ni][2], acc[mi][ni][3]};
                *(float2*)(g_p + (long)(rr + 8) * 256 + c) = o;
            }
        }
    }
}

// ---------------------------------------------------------------------------
// attention via bf16x3 mma. grid=(256,4), block=512 (16 warps).
// __launch_bounds__(512,1): full reg budget — the R7 64-reg cap spilled.
// Score: warps 2m x 8n. PV: split-K (2m x 2n x 4k) + slice reduction.
// ---------------------------------------------------------------------------
__global__ __launch_bounds__(512, 1) void attn_kernel(float* __restrict__ out)
{
    extern __shared__ char smc[];
    float* sc = (float*)smc;                                   // 64*264 f32
    __nv_bfloat16* wh = (__nv_bfloat16*)(smc + 64 * 264 * 4);  // 64*264
    __nv_bfloat16* wl = wh + 64 * 264;
    __nv_bfloat16* qh = wl + 64 * 264;                         // 64*72
    __nv_bfloat16* ql = qh + 64 * 72;
    __nv_bfloat16* kh = ql + 64 * 72;                          // 256*72
    __nv_bfloat16* kl = kh + 256 * 72;

    const int b  = blockIdx.x;
    const int tt = blockIdx.y;
    const int t0 = tt * 64;
    const int nst = tt + 1;
    const int send = nst * 64;
    const int tid = threadIdx.x, w = tid >> 5, lane = tid & 31;
    const int g = lane >> 2, l2 = lane & 3;

    const uint32_t qHa = smem_u32(qh), qLa = smem_u32(ql);
    const uint32_t kHa = smem_u32(kh), kLa = smem_u32(kl);
    const uint32_t wHa = smem_u32(wh), wLa = smem_u32(wl);

    // ---- load q tile (64x64) and live k rows, split hi/lo ----
    #pragma unroll
    for (int i = 0; i < 2; i++) {
        int f = tid + i * 512;
        int r = f >> 4, c4 = (f & 15) << 2;
        float4 v = *(const float4*)(g_q + ((long)(b * Tn + t0 + r)) * Hn + c4);
        __nv_bfloat16 h0, l0, h1, l1, h2, l2b, h3, l3;
        split_bf(v.x, h0, l0); split_bf(v.y, h1, l1);
        split_bf(v.z, h2, l2b); split_bf(v.w, h3, l3);
        *(uint2*)(qh + r * 72 + c4) = {pk(h0, h1), pk(h2, h3)};
        *(uint2*)(ql + r * 72 + c4) = {pk(l0, l1), pk(l2b, l3)};
    }
    for (int f = tid; f < send * 16; f += 512) {
        int r = f >> 4, c4 = (f & 15) << 2;
        float4 v = *(const float4*)(g_k + ((long)(b * Tn + r)) * Hn + c4);
        __nv_bfloat16 h0, l0, h1, l1, h2, l2b, h3, l3;
        split_bf(v.x, h0, l0); split_bf(v.y, h1, l1);
        split_bf(v.z, h2, l2b); split_bf(v.w, h3, l3);
        *(uint2*)(kh + r * 72 + c4) = {pk(h0, h1), pk(h2, h3)};
        *(uint2*)(kl + r * 72 + c4) = {pk(l0, l1), pk(l2b, l3)};
    }
    __syncthreads();

    // ---- score phase: warps 2m x 8n, one 32x32 tile each ----
    {
        const int wm = w >> 3, wn = w & 7;
        const int cb = wn * 32;                 // key-col base
        if (cb < send) {
            const int arow = wm * 32 + (lane & 15);
            const int acol = (lane >> 4) * 8;
            const int brow = cb + (lane & 7) + (lane >> 4) * 8;
            const int bcol = ((lane >> 3) & 1) * 8;
            float acc[2][4][4] = {};
            #pragma unroll
            for (int ks = 0; ks < 4; ks++) {
                uint32_t ah[2][4], al[2][4], bh[2][4], bl[2][4];
                #pragma unroll
                for (int mi = 0; mi < 2; mi++) {
                    uint32_t off = ((arow + mi * 16) * 72 + ks * 16 + acol) * 2;
                    ldsm4(ah[mi], qHa + off);
                    ldsm4(al[mi], qLa + off);
                }
                #pragma unroll
                for (int nj = 0; nj < 2; nj++) {
                    uint32_t off = ((brow + nj * 16) * 72 + ks * 16 + bcol) * 2;
                    ldsm4(bh[nj], kHa + off);
                    ldsm4(bl[nj], kLa + off);
                }
                #pragma unroll
                for (int mi = 0; mi < 2; mi++)
                    #pragma unroll
                    for (int ni = 0; ni < 4; ni++) {
                        const uint32_t* ph = &bh[ni >> 1][(ni & 1) * 2];
                        const uint32_t* pl = &bl[ni >> 1][(ni & 1) * 2];
                        mma_bf16(acc[mi][ni], ah[mi], ph);
                        mma_bf16(acc[mi][ni], ah[mi], pl);
                        mma_bf16(acc[mi][ni], al[mi], ph);
                    }
            }
            #pragma unroll
            for (int mi = 0; mi < 2; mi++)
                #pragma unroll
                for (int ni = 0; ni < 4; ni++) {
                    int rloc = wm * 32 + mi * 16 + g;
                    int sbase = cb + ni * 8 + l2 * 2;
                    #pragma unroll
                    for (int hf = 0; hf < 2; hf++) {
                        int row = rloc + hf * 8;
                        int t = t0 + row;
                        const float* prow = g_p + ((long)(b * Tn + t)) * 256;
                        float v0 = -1e30f, v1 = -1e30f;
                        if (sbase <= t)     v0 = acc[mi][ni][hf * 2]     + prow[sbase - t + 255];
                        if (sbase + 1 <= t) v1 = acc[mi][ni][hf * 2 + 1] + prow[sbase + 1 - t + 255];
                        float2 o = {v0, v1};
                        *(float2*)&sc[row * 264 + sbase] = o;
                    }
                }
        }
    }
    __syncthreads();   // scores complete; kh/kl free

    // ---- load live v rows into kh/kl (overlaps softmax) ----
    for (int f = tid; f < send * 16; f += 512) {
        int r = f >> 4, c4 = (f & 15) << 2;
        float4 v = *(const float4*)(g_v + ((long)(b * Tn + r)) * Hn + c4);
        __nv_bfloat16 h0, l0, h1, l1, h2, l2b, h3, l3;
        split_bf(v.x, h0, l0); split_bf(v.y, h1, l1);
        split_bf(v.z, h2, l2b); split_bf(v.w, h3, l3);
        *(uint2*)(kh + r * 72 + c4) = {pk(h0, h1), pk(h2, h3)};
        *(uint2*)(kl + r * 72 + c4) = {pk(l0, l1), pk(l2b, l3)};
    }

    // ---- softmax: 16 warps x 4 rows, bf16 hi/lo weight emit ----
    for (int r = w * 4; r < w * 4 + 4; r++) {
        float m = -1e30f;
        for (int i = 0; i < nst; i++) {
            float2 v = *(const float2*)&sc[r * 264 + i * 64 + lane * 2];
            m = fmaxf(m, fmaxf(v.x, v.y));
        }
        #pragma unroll
        for (int o = 16; o; o >>= 1) m = fmaxf(m, __shfl_xor_sync(0xffffffffu, m, o));
        float sum = 0.f;
        for (int i = 0; i < nst; i++) {
            float2 v = *(const float2*)&sc[r * 264 + i * 64 + lane * 2];
            v.x = __expf(v.x - m);
            v.y = __expf(v.y - m);
            sum += v.x + v.y;
            *(float2*)&sc[r * 264 + i * 64 + lane * 2] = v;
        }
        #pragma unroll
        for (int o = 16; o; o >>= 1) sum += __shfl_xor_sync(0xffffffffu, sum, o);
        float inv = 1.0f / sum;
        for (int i = 0; i < nst; i++) {
            float2 e = *(const float2*)&sc[r * 264 + i * 64 + lane * 2];
            float w0 = e.x * inv, w1 = e.y * inv;
            __nv_bfloat16 h0, l0, h1, l1;
            split_bf(w0, h0, l0);
            split_bf(w1, h1, l1);
            *(uint32_t*)&wh[r * 264 + i * 64 + lane * 2] = pk(h0, h1);
            *(uint32_t*)&wl[r * 264 + i * 64 + lane * 2] = pk(l0, l1);
        }
    }
    __syncthreads();   // weights + v ready; sc free

    // ---- out = wei @ v : split-K over warps (2m x 2n x 4k) ----
    {
        const int wk = w & 3;
        const int wn2 = (w >> 2) & 1;
        const int wm2 = w >> 3;
        if (wk < nst) {
            const int arow = wm2 * 32 + (lane & 15);
            const int acol = (lane >> 4) * 8;
            const int vrow = (lane & 7) + ((lane >> 3) & 1) * 8;
            const int vcol = wn2 * 32 + (lane >> 4) * 8;
            float oacc[2][4][4] = {};
            #pragma unroll
            for (int ks = 0; ks < 4; ks++) {
                uint32_t aw[2][4], awl[2][4], bvh[2][4], bvl[2][4];
                #pragma unroll
                for (int mi = 0; mi < 2; mi++) {
                    uint32_t aoff = ((arow + mi * 16) * 264 + wk * 64 + ks * 16 + acol) * 2;
                    ldsm4(aw[mi],  wHa + aoff);
                    ldsm4(awl[mi], wLa + aoff);
                }
                #pragma unroll
                for (int nj = 0; nj < 2; nj++) {
                    uint32_t voff = ((wk * 64 + ks * 16 + vrow) * 72 + vcol + nj * 16) * 2;
                    ldsm4t(bvh[nj], kHa + voff);
                    ldsm4t(bvl[nj], kLa + voff);
                }
                #pragma unroll
                for (int mi = 0; mi < 2; mi++)
                    #pragma unroll
                    for (int ni = 0; ni < 4; ni++) {
                        const uint32_t* ph = &bvh[ni >> 1][(ni & 1) * 2];
                        const uint32_t* pl = &bvl[ni >> 1][(ni & 1) * 2];
                        mma_bf16(oacc[mi][ni], aw[mi],  ph);
                        mma_bf16(oacc[mi][ni], aw[mi],  pl);
                        mma_bf16(oacc[mi][ni], awl[mi], ph);
                    }
            }
            // write slice wk to sc
            float* slice = sc + wk * 4096;
            #pragma unroll
            for (int mi = 0; mi < 2; mi++)
                #pragma unroll
                for (int ni = 0; ni < 4; ni++) {
                    int row = wm2 * 32 + mi * 16 + g;
                    int col = wn2 * 32 + ni * 8 + l2 * 2;
                    float2 o0 = {oacc[mi][ni][0], oacc[mi][ni][1]};
                    float2 o1 = {oacc[mi][ni][2], oacc[mi][ni][3]};
                    *(float2*)&slice[row * 64 + col] = o0;
                    *(float2*)&slice[(row + 8) * 64 + col] = o1;
                }
        }
    }
    __syncthreads();

    // ---- reduce nst slices and store ----
    #pragma unroll
    for (int i = 0; i < 8; i++) {
        int idx = tid + i * 512;
        float s = sc[idx];
        for (int j = 1; j < nst; j++) s += sc[j * 4096 + idx];
        int row = idx >> 6, col = idx & 63;
        out[((long)(b * Tn + t0 + row)) * Hn + col] = s;
    }
}

// ---------------------------------------------------------------------------
extern "C" void kernel_launch(void* const* d_in, const int* in_sizes, int n_in,
                              void* d_out, int out_size)
{
    const float* x  = (const float*)d_in[0];
    const float* Wk = (const float*)d_in[1];
    const float* Wq = (const float*)d_in[2];
    const float* Wv = (const float*)d_in[3];
    const float* E  = (const float*)d_in[4];
    float* out = (float*)d_out;

    setup_kernel<<<288, 256>>>(Wk, Wq, Wv, E);

    const int qkv_sm = (2 * 128 * 72 + 2 * 192 * 72) * (int)sizeof(__nv_bfloat16); // 92160
    cudaFuncSetAttribute(qkv_kernel, cudaFuncAttributeMaxDynamicSharedMemorySize, qkv_sm);
    qkv_kernel<<<Bn * Tn / 128, 512, qkv_sm>>>(x);

    const int pos_sm = (2 * 64 * 72 + 2 * 128 * 72) * (int)sizeof(__nv_bfloat16);  // 55296
    cudaFuncSetAttribute(pos_kernel, cudaFuncAttributeMaxDynamicSharedMemorySize, pos_sm);
    pos_kernel<<<dim3(Bn * Tn / 64, 2), 256, pos_sm>>>();

    const int attn_sm = 64 * 264 * 4 + 2 * 64 * 264 * 2 + 2 * 64 * 72 * 2
                      + 2 * 256 * 72 * 2;                                          // 227328
    cudaFuncSetAttribute(attn_kernel, cudaFuncAttributeMaxDynamicSharedMemorySize, attn_sm);
    attn_kernel<<<dim3(Bn, Tn / 64), 512, attn_sm>>>(out);
}